// round 7
// baseline (speedup 1.0000x reference)
#include <cuda_runtime.h>
#include <cuda_bf16.h>
#include <cuda_fp16.h>
#include <math.h>
#include <stdint.h>

// Problem constants
#define NMAX 50000
#define EMAX 800000
#define FDIM 128
#define SCAN_BLK 512

// ---------------- device scratch ----------------
__device__ float  g_q[NMAX * FDIM];
__device__ float  g_skip[NMAX * FDIM];
__device__ __half g_kv[NMAX * 256];     // per node: k[0..127] halves, v[0..127] halves
__device__ int    g_count[NMAX];
__device__ int    g_rowptr[NMAX + 1];
__device__ int    g_fill[NMAX];
__device__ int    g_esrc[EMAX];
__device__ int    g_bsum[1024];
__device__ int    g_boff[1024];

// ---------------- 1) mma.sync bf16 GEMM with 2-way bf16 split ----------------
#define APAD 40   // smem row stride in bf16 (80B) -> conflict-free frag loads

__device__ __forceinline__ void mma_bf16(float c[4], const uint32_t a[4], const uint32_t b[2]) {
    asm volatile(
        "mma.sync.aligned.m16n8k16.row.col.f32.bf16.bf16.f32 "
        "{%0,%1,%2,%3}, {%4,%5,%6,%7}, {%8,%9}, {%0,%1,%2,%3};"
        : "+f"(c[0]), "+f"(c[1]), "+f"(c[2]), "+f"(c[3])
        : "r"(a[0]), "r"(a[1]), "r"(a[2]), "r"(a[3]), "r"(b[0]), "r"(b[1]));
}

__global__ __launch_bounds__(256) void gemm_mma(
    const float* __restrict__ x,
    const float* __restrict__ Wq, const float* __restrict__ bq,
    const float* __restrict__ Wk, const float* __restrict__ bk,
    const float* __restrict__ Wv, const float* __restrict__ bv,
    const float* __restrict__ Ws, const float* __restrict__ bs,
    int M)
{
    __shared__ __nv_bfloat16 As_h[128 * APAD];
    __shared__ __nv_bfloat16 As_l[128 * APAD];
    __shared__ __nv_bfloat16 Bs_h[128 * APAD];
    __shared__ __nv_bfloat16 Bs_l[128 * APAD];

    const float* W;
    const float* bias;
    switch (blockIdx.y) {
        case 0:  W = Wq; bias = bq; break;
        case 1:  W = Wk; bias = bk; break;
        case 2:  W = Wv; bias = bv; break;
        default: W = Ws; bias = bs; break;
    }
    const bool to_half = (blockIdx.y == 1) || (blockIdx.y == 2);
    float* outf = (blockIdx.y == 0) ? g_q : g_skip;
    const int hbase = (blockIdx.y == 1) ? 0 : 128;

    const int tid  = threadIdx.x;
    const int wid  = tid >> 5;
    const int lane = tid & 31;
    const int wm   = wid >> 2;
    const int wn   = wid & 3;
    const int m0   = blockIdx.x * 128;
    const int qrow = lane >> 2;
    const int qk   = (lane & 3) * 2;

    float c[4][4][4];
    #pragma unroll
    for (int mi = 0; mi < 4; mi++)
        #pragma unroll
        for (int nj = 0; nj < 4; nj++)
            #pragma unroll
            for (int r = 0; r < 4; r++) c[mi][nj][r] = 0.f;

    for (int kt = 0; kt < 128; kt += 32) {
        #pragma unroll
        for (int r = 0; r < 4; r++) {
            const int f   = tid + 256 * r;
            const int row = f >> 3;
            const int c4  = (f & 7) * 4;
            float4 av = make_float4(0.f, 0.f, 0.f, 0.f);
            const int gm = m0 + row;
            if (gm < M) av = *(const float4*)(x + (size_t)gm * 128 + kt + c4);
            ushort4 h4, l4;
            {
                __nv_bfloat16 h;
                h = __float2bfloat16_rn(av.x); h4.x = __bfloat16_as_ushort(h);
                l4.x = __bfloat16_as_ushort(__float2bfloat16_rn(av.x - __bfloat162float(h)));
                h = __float2bfloat16_rn(av.y); h4.y = __bfloat16_as_ushort(h);
                l4.y = __bfloat16_as_ushort(__float2bfloat16_rn(av.y - __bfloat162float(h)));
                h = __float2bfloat16_rn(av.z); h4.z = __bfloat16_as_ushort(h);
                l4.z = __bfloat16_as_ushort(__float2bfloat16_rn(av.z - __bfloat162float(h)));
                h = __float2bfloat16_rn(av.w); h4.w = __bfloat16_as_ushort(h);
                l4.w = __bfloat16_as_ushort(__float2bfloat16_rn(av.w - __bfloat162float(h)));
            }
            *(ushort4*)(As_h + row * APAD + c4) = h4;
            *(ushort4*)(As_l + row * APAD + c4) = l4;
            const float4 bv4 = *(const float4*)(W + (size_t)row * 128 + kt + c4);
            {
                __nv_bfloat16 h;
                h = __float2bfloat16_rn(bv4.x); h4.x = __bfloat16_as_ushort(h);
                l4.x = __bfloat16_as_ushort(__float2bfloat16_rn(bv4.x - __bfloat162float(h)));
                h = __float2bfloat16_rn(bv4.y); h4.y = __bfloat16_as_ushort(h);
                l4.y = __bfloat16_as_ushort(__float2bfloat16_rn(bv4.y - __bfloat162float(h)));
                h = __float2bfloat16_rn(bv4.z); h4.z = __bfloat16_as_ushort(h);
                l4.z = __bfloat16_as_ushort(__float2bfloat16_rn(bv4.z - __bfloat162float(h)));
                h = __float2bfloat16_rn(bv4.w); h4.w = __bfloat16_as_ushort(h);
                l4.w = __bfloat16_as_ushort(__float2bfloat16_rn(bv4.w - __bfloat162float(h)));
            }
            *(ushort4*)(Bs_h + row * APAD + c4) = h4;
            *(ushort4*)(Bs_l + row * APAD + c4) = l4;
        }
        __syncthreads();

        #pragma unroll
        for (int pass = 0; pass < 3; pass++) {
            const __nv_bfloat16* Ab = (pass == 1) ? As_l : As_h;
            const __nv_bfloat16* Bb = (pass == 2) ? Bs_l : Bs_h;
            #pragma unroll
            for (int ks = 0; ks < 2; ks++) {
                const int kb = ks * 16 + qk;
                uint32_t a[4][4], b[4][2];
                #pragma unroll
                for (int mi = 0; mi < 4; mi++) {
                    const int row = wm * 64 + mi * 16 + qrow;
                    a[mi][0] = *(const uint32_t*)(Ab + row * APAD + kb);
                    a[mi][1] = *(const uint32_t*)(Ab + (row + 8) * APAD + kb);
                    a[mi][2] = *(const uint32_t*)(Ab + row * APAD + kb + 8);
                    a[mi][3] = *(const uint32_t*)(Ab + (row + 8) * APAD + kb + 8);
                }
                #pragma unroll
                for (int nj = 0; nj < 4; nj++) {
                    const int col = wn * 32 + nj * 8 + qrow;
                    b[nj][0] = *(const uint32_t*)(Bb + col * APAD + kb);
                    b[nj][1] = *(const uint32_t*)(Bb + col * APAD + kb + 8);
                }
                #pragma unroll
                for (int mi = 0; mi < 4; mi++)
                    #pragma unroll
                    for (int nj = 0; nj < 4; nj++)
                        mma_bf16(c[mi][nj], a[mi], b[nj]);
            }
        }
        __syncthreads();
    }

    float2 bj[4];
    #pragma unroll
    for (int nj = 0; nj < 4; nj++) {
        const int col = wn * 32 + nj * 8 + (lane & 3) * 2;
        bj[nj] = *(const float2*)(bias + col);
    }
    #pragma unroll
    for (int mi = 0; mi < 4; mi++) {
        const int r0 = m0 + wm * 64 + mi * 16 + qrow;
        #pragma unroll
        for (int nj = 0; nj < 4; nj++) {
            const int col = wn * 32 + nj * 8 + (lane & 3) * 2;
            const float v00 = c[mi][nj][0] + bj[nj].x;
            const float v01 = c[mi][nj][1] + bj[nj].y;
            const float v10 = c[mi][nj][2] + bj[nj].x;
            const float v11 = c[mi][nj][3] + bj[nj].y;
            if (to_half) {
                if (r0 < M)
                    *(__half2*)(g_kv + (size_t)r0 * 256 + hbase + col) = __floats2half2_rn(v00, v01);
                if (r0 + 8 < M)
                    *(__half2*)(g_kv + (size_t)(r0 + 8) * 256 + hbase + col) = __floats2half2_rn(v10, v11);
            } else {
                if (r0 < M)
                    *(float2*)(outf + (size_t)r0 * 128 + col) = make_float2(v00, v01);
                if (r0 + 8 < M)
                    *(float2*)(outf + (size_t)(r0 + 8) * 128 + col) = make_float2(v10, v11);
            }
        }
    }
}

// ---------------- 2) CSR build ----------------
__global__ void zero_counts(int n)
{
    int i = blockIdx.x * blockDim.x + threadIdx.x;
    if (i < n) g_count[i] = 0;
}

__global__ void hist_kernel(const int* __restrict__ ei, int e)
{
    int i = blockIdx.x * blockDim.x + threadIdx.x;
    if (i < e) atomicAdd(&g_count[ei[e + i]], 1);
}

__global__ void scan_blocks(int n)
{
    __shared__ int sh[SCAN_BLK];
    const int t = threadIdx.x;
    const int i = blockIdx.x * SCAN_BLK + t;
    const int v = (i < n) ? g_count[i] : 0;
    sh[t] = v;
    __syncthreads();
    #pragma unroll
    for (int off = 1; off < SCAN_BLK; off <<= 1) {
        int u = (t >= off) ? sh[t - off] : 0;
        __syncthreads();
        sh[t] += u;
        __syncthreads();
    }
    if (i < n) g_rowptr[i] = sh[t] - v;
    if (t == SCAN_BLK - 1) g_bsum[blockIdx.x] = sh[t];
}

__global__ void scan_tops(int nb, int n)
{
    __shared__ int sh[SCAN_BLK];
    const int t = threadIdx.x;
    const int v = (t < nb) ? g_bsum[t] : 0;
    sh[t] = v;
    __syncthreads();
    #pragma unroll
    for (int off = 1; off < SCAN_BLK; off <<= 1) {
        int u = (t >= off) ? sh[t - off] : 0;
        __syncthreads();
        sh[t] += u;
        __syncthreads();
    }
    g_boff[t] = sh[t] - v;
    if (t == SCAN_BLK - 1) g_rowptr[n] = sh[t];
}

__global__ void add_offsets(int n)
{
    const int i = blockIdx.x * blockDim.x + threadIdx.x;
    if (i < n) {
        const int r = g_rowptr[i] + g_boff[i / SCAN_BLK];
        g_rowptr[i] = r;
        g_fill[i]   = r;
    }
}

__global__ void scatter_kernel(const int* __restrict__ ei, int e)
{
    int i = blockIdx.x * blockDim.x + threadIdx.x;
    if (i < e) {
        int dst  = ei[e + i];
        int slot = atomicAdd(&g_fill[dst], 1);
        g_esrc[slot] = ei[i];
    }
}

// ---------------- 3) fused attention aggregation (2 warps per dst node) ----------------
// Warp pair shares a node: warp `half` takes edges beg+half, beg+half+2, ...
// (each with a 2-edge unroll => 4 chains in flight per node). Partials combine
// through smem; the even warp finishes normalize + skip + relu + store.
__global__ __launch_bounds__(256) void edge_attn(float* __restrict__ out, int n)
{
    __shared__ float  sden[4 * 32];
    __shared__ float4 sacc[4 * 32];

    const int wInB = threadIdx.x >> 5;      // 0..7
    const int lane = threadIdx.x & 31;
    const int pair = wInB >> 1;             // 0..3
    const int half = wInB & 1;
    const int node = blockIdx.x * 4 + pair;
    const bool valid = node < n;

    const float scale = 0.17677669529663687f;  // 1/sqrt(32)
    float4 q4 = make_float4(0.f, 0.f, 0.f, 0.f);
    int beg = 0, end = 0;
    if (valid) {
        q4 = *(const float4*)(g_q + (size_t)node * 128 + lane * 4);
        q4.x *= scale; q4.y *= scale; q4.z *= scale; q4.w *= scale;
        beg = g_rowptr[node];
        end = g_rowptr[node + 1];
    }

    float4 acc = make_float4(0.f, 0.f, 0.f, 0.f);
    float den = 0.f;

    int i = beg + half;
    for (; i + 2 < end; i += 4) {           // pair (i, i+2), both < end
        const int s0 = __ldg(&g_esrc[i]);
        const int s1 = __ldg(&g_esrc[i + 2]);
        const uint2 k0u = *(const uint2*)(g_kv + (size_t)s0 * 256 + lane * 4);
        const uint2 k1u = *(const uint2*)(g_kv + (size_t)s1 * 256 + lane * 4);
        const float2 k0a = __half22float2(*(const __half2*)&k0u.x);
        const float2 k0b = __half22float2(*(const __half2*)&k0u.y);
        const float2 k1a = __half22float2(*(const __half2*)&k1u.x);
        const float2 k1b = __half22float2(*(const __half2*)&k1u.y);
        float p0 = q4.x * k0a.x + q4.y * k0a.y + q4.z * k0b.x + q4.w * k0b.y;
        float p1 = q4.x * k1a.x + q4.y * k1a.y + q4.z * k1b.x + q4.w * k1b.y;
        p0 += __shfl_xor_sync(0xffffffffu, p0, 1, 8);
        p1 += __shfl_xor_sync(0xffffffffu, p1, 1, 8);
        p0 += __shfl_xor_sync(0xffffffffu, p0, 2, 8);
        p1 += __shfl_xor_sync(0xffffffffu, p1, 2, 8);
        p0 += __shfl_xor_sync(0xffffffffu, p0, 4, 8);
        p1 += __shfl_xor_sync(0xffffffffu, p1, 4, 8);
        const float w0 = __expf(p0);
        const float w1 = __expf(p1);
        const uint2 v0u = *(const uint2*)(g_kv + (size_t)s0 * 256 + 128 + lane * 4);
        const uint2 v1u = *(const uint2*)(g_kv + (size_t)s1 * 256 + 128 + lane * 4);
        const float2 v0a = __half22float2(*(const __half2*)&v0u.x);
        const float2 v0b = __half22float2(*(const __half2*)&v0u.y);
        const float2 v1a = __half22float2(*(const __half2*)&v1u.x);
        const float2 v1b = __half22float2(*(const __half2*)&v1u.y);
        den += w0 + w1;
        acc.x = fmaf(w0, v0a.x, fmaf(w1, v1a.x, acc.x));
        acc.y = fmaf(w0, v0a.y, fmaf(w1, v1a.y, acc.y));
        acc.z = fmaf(w0, v0b.x, fmaf(w1, v1b.x, acc.z));
        acc.w = fmaf(w0, v0b.y, fmaf(w1, v1b.y, acc.w));
    }
    if (i < end) {
        const int s0 = __ldg(&g_esrc[i]);
        const uint2 k0u = *(const uint2*)(g_kv + (size_t)s0 * 256 + lane * 4);
        const float2 k0a = __half22float2(*(const __half2*)&k0u.x);
        const float2 k0b = __half22float2(*(const __half2*)&k0u.y);
        float p0 = q4.x * k0a.x + q4.y * k0a.y + q4.z * k0b.x + q4.w * k0b.y;
        p0 += __shfl_xor_sync(0xffffffffu, p0, 1, 8);
        p0 += __shfl_xor_sync(0xffffffffu, p0, 2, 8);
        p0 += __shfl_xor_sync(0xffffffffu, p0, 4, 8);
        const float w0 = __expf(p0);
        const uint2 v0u = *(const uint2*)(g_kv + (size_t)s0 * 256 + 128 + lane * 4);
        const float2 v0a = __half22float2(*(const __half2*)&v0u.x);
        const float2 v0b = __half22float2(*(const __half2*)&v0u.y);
        den += w0;
        acc.x = fmaf(w0, v0a.x, acc.x);
        acc.y = fmaf(w0, v0a.y, acc.y);
        acc.z = fmaf(w0, v0b.x, acc.z);
        acc.w = fmaf(w0, v0b.y, acc.w);
    }

    // combine warp pair via smem
    if (half == 1) {
        sden[pair * 32 + lane] = den;
        sacc[pair * 32 + lane] = acc;
    }
    __syncthreads();
    if (half == 0 && valid) {
        den += sden[pair * 32 + lane];
        const float4 a1 = sacc[pair * 32 + lane];
        acc.x += a1.x; acc.y += a1.y; acc.z += a1.z; acc.w += a1.w;

        const float inv = (den > 0.f) ? (1.0f / den) : 0.f;
        const float4 sk = *(const float4*)(g_skip + (size_t)node * 128 + lane * 4);
        float4 o;
        o.x = fmaxf(fmaf(acc.x, inv, sk.x), 0.f);
        o.y = fmaxf(fmaf(acc.y, inv, sk.y), 0.f);
        o.z = fmaxf(fmaf(acc.z, inv, sk.z), 0.f);
        o.w = fmaxf(fmaf(acc.w, inv, sk.w), 0.f);
        *(float4*)(out + (size_t)node * 128 + lane * 4) = o;
    }
}

// ---------------- host launcher ----------------
extern "C" void kernel_launch(void* const* d_in, const int* in_sizes, int n_in,
                              void* d_out, int out_size)
{
    const float* x  = (const float*)d_in[0];
    const int*   ei = (const int*)  d_in[1];
    const float* Wq = (const float*)d_in[2];
    const float* bq = (const float*)d_in[3];
    const float* Wk = (const float*)d_in[4];
    const float* bk = (const float*)d_in[5];
    const float* Wv = (const float*)d_in[6];
    const float* bv = (const float*)d_in[7];
    const float* Ws = (const float*)d_in[8];
    const float* bs = (const float*)d_in[9];
    float* out = (float*)d_out;

    const int n = in_sizes[0] / FDIM;   // 50000
    const int e = in_sizes[1] / 2;      // 800000
    const int nb = (n + SCAN_BLK - 1) / SCAN_BLK;

    // Side stream: CSR build overlaps the GEMM.
    cudaStream_t s2;
    cudaEvent_t ev0, ev1;
    cudaStreamCreateWithFlags(&s2, cudaStreamNonBlocking);
    cudaEventCreateWithFlags(&ev0, cudaEventDisableTiming);
    cudaEventCreateWithFlags(&ev1, cudaEventDisableTiming);

    cudaEventRecord(ev0, 0);
    cudaStreamWaitEvent(s2, ev0, 0);

    zero_counts<<<(n + 255) / 256, 256, 0, s2>>>(n);
    hist_kernel<<<(e + 255) / 256, 256, 0, s2>>>(ei, e);
    scan_blocks<<<nb, SCAN_BLK, 0, s2>>>(n);
    scan_tops<<<1, SCAN_BLK, 0, s2>>>(nb, n);
    add_offsets<<<(n + 255) / 256, 256, 0, s2>>>(n);
    scatter_kernel<<<(e + 255) / 256, 256, 0, s2>>>(ei, e);
    cudaEventRecord(ev1, s2);

    dim3 gg((n + 127) / 128, 4);
    gemm_mma<<<gg, 256>>>(x, Wq, bq, Wk, bk, Wv, bv, Ws, bs, n);

    cudaStreamWaitEvent(0, ev1, 0);
    edge_attn<<<(n + 3) / 4, 256>>>(out, n);
}

// round 8
// speedup vs baseline: 1.0620x; 1.0620x over previous
#include <cuda_runtime.h>
#include <cuda_bf16.h>
#include <cuda_fp16.h>
#include <math.h>
#include <stdint.h>

// Problem constants
#define NMAX 50000
#define EMAX 800000
#define FDIM 128
#define SCAN_BLK 512

// ---------------- device scratch ----------------
__device__ float  g_q[NMAX * FDIM];
__device__ float  g_skip[NMAX * FDIM];
// Interleaved kv: per node 256 halves; lane-l group at l*8: [k(4l..4l+3) | v(4l..4l+3)]
__device__ __half g_kv[NMAX * 256];
__device__ int    g_count[NMAX];
__device__ int    g_rowptr[NMAX + 1];
__device__ int    g_fill[NMAX];
__device__ int    g_esrc[EMAX];
__device__ int    g_bsum[1024];
__device__ int    g_boff[1024];

// ---------------- 1) mma.sync bf16 GEMM with 2-way bf16 split ----------------
#define APAD 40   // smem row stride in bf16 (80B) -> conflict-free frag loads

__device__ __forceinline__ void mma_bf16(float c[4], const uint32_t a[4], const uint32_t b[2]) {
    asm volatile(
        "mma.sync.aligned.m16n8k16.row.col.f32.bf16.bf16.f32 "
        "{%0,%1,%2,%3}, {%4,%5,%6,%7}, {%8,%9}, {%0,%1,%2,%3};"
        : "+f"(c[0]), "+f"(c[1]), "+f"(c[2]), "+f"(c[3])
        : "r"(a[0]), "r"(a[1]), "r"(a[2]), "r"(a[3]), "r"(b[0]), "r"(b[1]));
}

__global__ __launch_bounds__(256) void gemm_mma(
    const float* __restrict__ x,
    const float* __restrict__ Wq, const float* __restrict__ bq,
    const float* __restrict__ Wk, const float* __restrict__ bk,
    const float* __restrict__ Wv, const float* __restrict__ bv,
    const float* __restrict__ Ws, const float* __restrict__ bs,
    int M)
{
    __shared__ __nv_bfloat16 As_h[128 * APAD];
    __shared__ __nv_bfloat16 As_l[128 * APAD];
    __shared__ __nv_bfloat16 Bs_h[128 * APAD];
    __shared__ __nv_bfloat16 Bs_l[128 * APAD];

    const float* W;
    const float* bias;
    switch (blockIdx.y) {
        case 0:  W = Wq; bias = bq; break;
        case 1:  W = Wk; bias = bk; break;
        case 2:  W = Wv; bias = bv; break;
        default: W = Ws; bias = bs; break;
    }
    const bool to_half = (blockIdx.y == 1) || (blockIdx.y == 2);
    float* outf = (blockIdx.y == 0) ? g_q : g_skip;
    const int hsub = (blockIdx.y == 1) ? 0 : 4;   // k -> first 4 halves, v -> last 4

    const int tid  = threadIdx.x;
    const int wid  = tid >> 5;
    const int lane = tid & 31;
    const int wm   = wid >> 2;
    const int wn   = wid & 3;
    const int m0   = blockIdx.x * 128;
    const int qrow = lane >> 2;
    const int qk   = (lane & 3) * 2;

    float c[4][4][4];
    #pragma unroll
    for (int mi = 0; mi < 4; mi++)
        #pragma unroll
        for (int nj = 0; nj < 4; nj++)
            #pragma unroll
            for (int r = 0; r < 4; r++) c[mi][nj][r] = 0.f;

    for (int kt = 0; kt < 128; kt += 32) {
        #pragma unroll
        for (int r = 0; r < 4; r++) {
            const int f   = tid + 256 * r;
            const int row = f >> 3;
            const int c4  = (f & 7) * 4;
            float4 av = make_float4(0.f, 0.f, 0.f, 0.f);
            const int gm = m0 + row;
            if (gm < M) av = *(const float4*)(x + (size_t)gm * 128 + kt + c4);
            ushort4 h4, l4;
            {
                __nv_bfloat16 h;
                h = __float2bfloat16_rn(av.x); h4.x = __bfloat16_as_ushort(h);
                l4.x = __bfloat16_as_ushort(__float2bfloat16_rn(av.x - __bfloat162float(h)));
                h = __float2bfloat16_rn(av.y); h4.y = __bfloat16_as_ushort(h);
                l4.y = __bfloat16_as_ushort(__float2bfloat16_rn(av.y - __bfloat162float(h)));
                h = __float2bfloat16_rn(av.z); h4.z = __bfloat16_as_ushort(h);
                l4.z = __bfloat16_as_ushort(__float2bfloat16_rn(av.z - __bfloat162float(h)));
                h = __float2bfloat16_rn(av.w); h4.w = __bfloat16_as_ushort(h);
                l4.w = __bfloat16_as_ushort(__float2bfloat16_rn(av.w - __bfloat162float(h)));
            }
            *(ushort4*)(As_h + row * APAD + c4) = h4;
            *(ushort4*)(As_l + row * APAD + c4) = l4;
            const float4 bv4 = *(const float4*)(W + (size_t)row * 128 + kt + c4);
            {
                __nv_bfloat16 h;
                h = __float2bfloat16_rn(bv4.x); h4.x = __bfloat16_as_ushort(h);
                l4.x = __bfloat16_as_ushort(__float2bfloat16_rn(bv4.x - __bfloat162float(h)));
                h = __float2bfloat16_rn(bv4.y); h4.y = __bfloat16_as_ushort(h);
                l4.y = __bfloat16_as_ushort(__float2bfloat16_rn(bv4.y - __bfloat162float(h)));
                h = __float2bfloat16_rn(bv4.z); h4.z = __bfloat16_as_ushort(h);
                l4.z = __bfloat16_as_ushort(__float2bfloat16_rn(bv4.z - __bfloat162float(h)));
                h = __float2bfloat16_rn(bv4.w); h4.w = __bfloat16_as_ushort(h);
                l4.w = __bfloat16_as_ushort(__float2bfloat16_rn(bv4.w - __bfloat162float(h)));
            }
            *(ushort4*)(Bs_h + row * APAD + c4) = h4;
            *(ushort4*)(Bs_l + row * APAD + c4) = l4;
        }
        __syncthreads();

        #pragma unroll
        for (int pass = 0; pass < 3; pass++) {
            const __nv_bfloat16* Ab = (pass == 1) ? As_l : As_h;
            const __nv_bfloat16* Bb = (pass == 2) ? Bs_l : Bs_h;
            #pragma unroll
            for (int ks = 0; ks < 2; ks++) {
                const int kb = ks * 16 + qk;
                uint32_t a[4][4], b[4][2];
                #pragma unroll
                for (int mi = 0; mi < 4; mi++) {
                    const int row = wm * 64 + mi * 16 + qrow;
                    a[mi][0] = *(const uint32_t*)(Ab + row * APAD + kb);
                    a[mi][1] = *(const uint32_t*)(Ab + (row + 8) * APAD + kb);
                    a[mi][2] = *(const uint32_t*)(Ab + row * APAD + kb + 8);
                    a[mi][3] = *(const uint32_t*)(Ab + (row + 8) * APAD + kb + 8);
                }
                #pragma unroll
                for (int nj = 0; nj < 4; nj++) {
                    const int col = wn * 32 + nj * 8 + qrow;
                    b[nj][0] = *(const uint32_t*)(Bb + col * APAD + kb);
                    b[nj][1] = *(const uint32_t*)(Bb + col * APAD + kb + 8);
                }
                #pragma unroll
                for (int mi = 0; mi < 4; mi++)
                    #pragma unroll
                    for (int nj = 0; nj < 4; nj++)
                        mma_bf16(c[mi][nj], a[mi], b[nj]);
            }
        }
        __syncthreads();
    }

    float2 bj[4];
    #pragma unroll
    for (int nj = 0; nj < 4; nj++) {
        const int col = wn * 32 + nj * 8 + (lane & 3) * 2;
        bj[nj] = *(const float2*)(bias + col);
    }
    #pragma unroll
    for (int mi = 0; mi < 4; mi++) {
        const int r0 = m0 + wm * 64 + mi * 16 + qrow;
        #pragma unroll
        for (int nj = 0; nj < 4; nj++) {
            const int col = wn * 32 + nj * 8 + (lane & 3) * 2;
            const float v00 = c[mi][nj][0] + bj[nj].x;
            const float v01 = c[mi][nj][1] + bj[nj].y;
            const float v10 = c[mi][nj][2] + bj[nj].x;
            const float v11 = c[mi][nj][3] + bj[nj].y;
            if (to_half) {
                // interleaved record offset: 4-half k/v subgroups per lane-channel group
                const int off = ((col >> 2) << 3) + (col & 3) + hsub;
                if (r0 < M)
                    *(__half2*)(g_kv + (size_t)r0 * 256 + off) = __floats2half2_rn(v00, v01);
                if (r0 + 8 < M)
                    *(__half2*)(g_kv + (size_t)(r0 + 8) * 256 + off) = __floats2half2_rn(v10, v11);
            } else {
                if (r0 < M)
                    *(float2*)(outf + (size_t)r0 * 128 + col) = make_float2(v00, v01);
                if (r0 + 8 < M)
                    *(float2*)(outf + (size_t)(r0 + 8) * 128 + col) = make_float2(v10, v11);
            }
        }
    }
}

// ---------------- 2) CSR build ----------------
__global__ void zero_counts(int n)
{
    int i = blockIdx.x * blockDim.x + threadIdx.x;
    if (i < n) g_count[i] = 0;
}

__global__ void hist_kernel(const int* __restrict__ ei, int e)
{
    int i = blockIdx.x * blockDim.x + threadIdx.x;
    if (i < e) atomicAdd(&g_count[ei[e + i]], 1);
}

__global__ void scan_blocks(int n)
{
    __shared__ int sh[SCAN_BLK];
    const int t = threadIdx.x;
    const int i = blockIdx.x * SCAN_BLK + t;
    const int v = (i < n) ? g_count[i] : 0;
    sh[t] = v;
    __syncthreads();
    #pragma unroll
    for (int off = 1; off < SCAN_BLK; off <<= 1) {
        int u = (t >= off) ? sh[t - off] : 0;
        __syncthreads();
        sh[t] += u;
        __syncthreads();
    }
    if (i < n) g_rowptr[i] = sh[t] - v;
    if (t == SCAN_BLK - 1) g_bsum[blockIdx.x] = sh[t];
}

__global__ void scan_tops(int nb, int n)
{
    __shared__ int sh[SCAN_BLK];
    const int t = threadIdx.x;
    const int v = (t < nb) ? g_bsum[t] : 0;
    sh[t] = v;
    __syncthreads();
    #pragma unroll
    for (int off = 1; off < SCAN_BLK; off <<= 1) {
        int u = (t >= off) ? sh[t - off] : 0;
        __syncthreads();
        sh[t] += u;
        __syncthreads();
    }
    g_boff[t] = sh[t] - v;
    if (t == SCAN_BLK - 1) g_rowptr[n] = sh[t];
}

__global__ void add_offsets(int n)
{
    const int i = blockIdx.x * blockDim.x + threadIdx.x;
    if (i < n) {
        const int r = g_rowptr[i] + g_boff[i / SCAN_BLK];
        g_rowptr[i] = r;
        g_fill[i]   = r;
    }
}

__global__ void scatter_kernel(const int* __restrict__ ei, int e)
{
    int i = blockIdx.x * blockDim.x + threadIdx.x;
    if (i < e) {
        int dst  = ei[e + i];
        int slot = atomicAdd(&g_fill[dst], 1);
        g_esrc[slot] = ei[i];
    }
}

// ---------------- 3) fused attention aggregation (warp per dst node) ----------------
// One LDG.128 per edge per lane fetches both k and v (interleaved layout).
__global__ __launch_bounds__(256) void edge_attn(float* __restrict__ out, int n)
{
    const int warp = (blockIdx.x * blockDim.x + threadIdx.x) >> 5;
    const int lane = threadIdx.x & 31;
    if (warp >= n) return;
    const int node = warp;

    const float scale = 0.17677669529663687f;  // 1/sqrt(32)
    float4 q4 = *(const float4*)(g_q + (size_t)node * 128 + lane * 4);
    q4.x *= scale; q4.y *= scale; q4.z *= scale; q4.w *= scale;

    float4 acc = make_float4(0.f, 0.f, 0.f, 0.f);
    float den = 0.f;

    const int beg = g_rowptr[node];
    const int end = g_rowptr[node + 1];

    int i = beg;
    for (; i + 2 <= end; i += 2) {
        const int s0 = __ldg(&g_esrc[i]);
        const int s1 = __ldg(&g_esrc[i + 1]);
        const uint4 kv0 = *(const uint4*)(g_kv + (size_t)s0 * 256 + lane * 8);
        const uint4 kv1 = *(const uint4*)(g_kv + (size_t)s1 * 256 + lane * 8);
        const float2 k0a = __half22float2(*(const __half2*)&kv0.x);
        const float2 k0b = __half22float2(*(const __half2*)&kv0.y);
        const float2 k1a = __half22float2(*(const __half2*)&kv1.x);
        const float2 k1b = __half22float2(*(const __half2*)&kv1.y);
        float p0 = q4.x * k0a.x + q4.y * k0a.y + q4.z * k0b.x + q4.w * k0b.y;
        float p1 = q4.x * k1a.x + q4.y * k1a.y + q4.z * k1b.x + q4.w * k1b.y;
        p0 += __shfl_xor_sync(0xffffffffu, p0, 1, 8);
        p1 += __shfl_xor_sync(0xffffffffu, p1, 1, 8);
        p0 += __shfl_xor_sync(0xffffffffu, p0, 2, 8);
        p1 += __shfl_xor_sync(0xffffffffu, p1, 2, 8);
        p0 += __shfl_xor_sync(0xffffffffu, p0, 4, 8);
        p1 += __shfl_xor_sync(0xffffffffu, p1, 4, 8);
        const float w0 = __expf(p0);
        const float w1 = __expf(p1);
        const float2 v0a = __half22float2(*(const __half2*)&kv0.z);
        const float2 v0b = __half22float2(*(const __half2*)&kv0.w);
        const float2 v1a = __half22float2(*(const __half2*)&kv1.z);
        const float2 v1b = __half22float2(*(const __half2*)&kv1.w);
        den += w0 + w1;
        acc.x = fmaf(w0, v0a.x, fmaf(w1, v1a.x, acc.x));
        acc.y = fmaf(w0, v0a.y, fmaf(w1, v1a.y, acc.y));
        acc.z = fmaf(w0, v0b.x, fmaf(w1, v1b.x, acc.z));
        acc.w = fmaf(w0, v0b.y, fmaf(w1, v1b.y, acc.w));
    }
    if (i < end) {
        const int s0 = __ldg(&g_esrc[i]);
        const uint4 kv0 = *(const uint4*)(g_kv + (size_t)s0 * 256 + lane * 8);
        const float2 k0a = __half22float2(*(const __half2*)&kv0.x);
        const float2 k0b = __half22float2(*(const __half2*)&kv0.y);
        float p0 = q4.x * k0a.x + q4.y * k0a.y + q4.z * k0b.x + q4.w * k0b.y;
        p0 += __shfl_xor_sync(0xffffffffu, p0, 1, 8);
        p0 += __shfl_xor_sync(0xffffffffu, p0, 2, 8);
        p0 += __shfl_xor_sync(0xffffffffu, p0, 4, 8);
        const float w0 = __expf(p0);
        const float2 v0a = __half22float2(*(const __half2*)&kv0.z);
        const float2 v0b = __half22float2(*(const __half2*)&kv0.w);
        den += w0;
        acc.x = fmaf(w0, v0a.x, acc.x);
        acc.y = fmaf(w0, v0a.y, acc.y);
        acc.z = fmaf(w0, v0b.x, acc.z);
        acc.w = fmaf(w0, v0b.y, acc.w);
    }

    const float inv = (den > 0.f) ? (1.0f / den) : 0.f;
    const float4 sk = *(const float4*)(g_skip + (size_t)node * 128 + lane * 4);
    float4 o;
    o.x = fmaxf(fmaf(acc.x, inv, sk.x), 0.f);
    o.y = fmaxf(fmaf(acc.y, inv, sk.y), 0.f);
    o.z = fmaxf(fmaf(acc.z, inv, sk.z), 0.f);
    o.w = fmaxf(fmaf(acc.w, inv, sk.w), 0.f);
    *(float4*)(out + (size_t)node * 128 + lane * 4) = o;
}

// ---------------- host launcher ----------------
extern "C" void kernel_launch(void* const* d_in, const int* in_sizes, int n_in,
                              void* d_out, int out_size)
{
    const float* x  = (const float*)d_in[0];
    const int*   ei = (const int*)  d_in[1];
    const float* Wq = (const float*)d_in[2];
    const float* bq = (const float*)d_in[3];
    const float* Wk = (const float*)d_in[4];
    const float* bk = (const float*)d_in[5];
    const float* Wv = (const float*)d_in[6];
    const float* bv = (const float*)d_in[7];
    const float* Ws = (const float*)d_in[8];
    const float* bs = (const float*)d_in[9];
    float* out = (float*)d_out;

    const int n = in_sizes[0] / FDIM;   // 50000
    const int e = in_sizes[1] / 2;      // 800000
    const int nb = (n + SCAN_BLK - 1) / SCAN_BLK;

    // Side stream: CSR build overlaps the GEMM.
    cudaStream_t s2;
    cudaEvent_t ev0, ev1;
    cudaStreamCreateWithFlags(&s2, cudaStreamNonBlocking);
    cudaEventCreateWithFlags(&ev0, cudaEventDisableTiming);
    cudaEventCreateWithFlags(&ev1, cudaEventDisableTiming);

    cudaEventRecord(ev0, 0);
    cudaStreamWaitEvent(s2, ev0, 0);

    zero_counts<<<(n + 255) / 256, 256, 0, s2>>>(n);
    hist_kernel<<<(e + 255) / 256, 256, 0, s2>>>(ei, e);
    scan_blocks<<<nb, SCAN_BLK, 0, s2>>>(n);
    scan_tops<<<1, SCAN_BLK, 0, s2>>>(nb, n);
    add_offsets<<<(n + 255) / 256, 256, 0, s2>>>(n);
    scatter_kernel<<<(e + 255) / 256, 256, 0, s2>>>(ei, e);
    cudaEventRecord(ev1, s2);

    dim3 gg((n + 127) / 128, 4);
    gemm_mma<<<gg, 256>>>(x, Wq, bq, Wk, bk, Wv, bv, Ws, bs, n);

    cudaStreamWaitEvent(0, ev1, 0);
    edge_attn<<<(n * 32 + 255) / 256, 256>>>(out, n);
}

// round 9
// speedup vs baseline: 1.1180x; 1.0528x over previous
#include <cuda_runtime.h>
#include <cuda_bf16.h>
#include <cuda_fp16.h>
#include <math.h>
#include <stdint.h>

// Problem constants
#define NMAX 50000
#define EMAX 800000
#define FDIM 128
#define SCAN_BLK 512
#define MPAD 128   // row padding so cp.async can safely over-read the last tile

// ---------------- device scratch ----------------
__device__ float  g_q[NMAX * FDIM];
__device__ float  g_skip[NMAX * FDIM];
// Interleaved kv: per node 256 halves; lane-l group at l*8: [k(4l..4l+3) | v(4l..4l+3)]
__device__ __half g_kv[NMAX * 256];
// Pre-split bf16 operands (hi/lo) for the GEMM
__device__ __nv_bfloat16 g_xh[(NMAX + MPAD) * FDIM];
__device__ __nv_bfloat16 g_xl[(NMAX + MPAD) * FDIM];
__device__ __nv_bfloat16 g_wh[512 * FDIM];
__device__ __nv_bfloat16 g_wl[512 * FDIM];
__device__ int    g_count[NMAX];
__device__ int    g_rowptr[NMAX + 1];
__device__ int    g_fill[NMAX];
__device__ int    g_esrc[EMAX];
__device__ int    g_bsum[1024];
__device__ int    g_boff[1024];

// ---------------- helpers ----------------
__device__ __forceinline__ uint32_t smem_u32(const void* p) {
    uint32_t a;
    asm("{ .reg .u64 t; cvta.to.shared.u64 t, %1; cvt.u32.u64 %0, t; }" : "=r"(a) : "l"(p));
    return a;
}
__device__ __forceinline__ void cp16(uint32_t dst, const void* src) {
    asm volatile("cp.async.cg.shared.global [%0], [%1], 16;" :: "r"(dst), "l"(src));
}
__device__ __forceinline__ void split4(float4 v, ushort4& h4, ushort4& l4) {
    __nv_bfloat16 h;
    h = __float2bfloat16_rn(v.x); h4.x = __bfloat16_as_ushort(h);
    l4.x = __bfloat16_as_ushort(__float2bfloat16_rn(v.x - __bfloat162float(h)));
    h = __float2bfloat16_rn(v.y); h4.y = __bfloat16_as_ushort(h);
    l4.y = __bfloat16_as_ushort(__float2bfloat16_rn(v.y - __bfloat162float(h)));
    h = __float2bfloat16_rn(v.z); h4.z = __bfloat16_as_ushort(h);
    l4.z = __bfloat16_as_ushort(__float2bfloat16_rn(v.z - __bfloat162float(h)));
    h = __float2bfloat16_rn(v.w); h4.w = __bfloat16_as_ushort(h);
    l4.w = __bfloat16_as_ushort(__float2bfloat16_rn(v.w - __bfloat162float(h)));
}

// ---------------- 0) split x / W into bf16 hi+lo ----------------
__global__ void split_x(const float* __restrict__ x, int n)
{
    const int i = blockIdx.x * blockDim.x + threadIdx.x;   // over n*32 float4s
    if (i >= n * (FDIM / 4)) return;
    float4 v = *(const float4*)(x + (size_t)i * 4);
    ushort4 h4, l4;
    split4(v, h4, l4);
    *(ushort4*)(g_xh + (size_t)i * 4) = h4;
    *(ushort4*)(g_xl + (size_t)i * 4) = l4;
}

__global__ void split_w(const float* __restrict__ Wq, const float* __restrict__ Wk,
                        const float* __restrict__ Wv, const float* __restrict__ Ws)
{
    const int i = blockIdx.x * blockDim.x + threadIdx.x;   // over 512*32 float4s
    if (i >= 512 * (FDIM / 4)) return;
    const int m = i >> 12;                                  // /4096 float4s per matrix
    const int r = i & 4095;
    const float* W = (m == 0) ? Wq : (m == 1) ? Wk : (m == 2) ? Wv : Ws;
    float4 v = *(const float4*)(W + (size_t)r * 4);
    ushort4 h4, l4;
    split4(v, h4, l4);
    *(ushort4*)(g_wh + (size_t)i * 4) = h4;
    *(ushort4*)(g_wl + (size_t)i * 4) = l4;
}

// ---------------- 1) cp.async-pipelined bf16 mma GEMM ----------------
// BK=16, 2 stages, APAD=24 halves (48B row stride -> conflict-free frag LDS).
#define APAD16 24
#define NTILE  8    // 128 / 16

__device__ __forceinline__ void mma_bf16(float c[4], const uint32_t a[4], const uint32_t b[2]) {
    asm volatile(
        "mma.sync.aligned.m16n8k16.row.col.f32.bf16.bf16.f32 "
        "{%0,%1,%2,%3}, {%4,%5,%6,%7}, {%8,%9}, {%0,%1,%2,%3};"
        : "+f"(c[0]), "+f"(c[1]), "+f"(c[2]), "+f"(c[3])
        : "r"(a[0]), "r"(a[1]), "r"(a[2]), "r"(a[3]), "r"(b[0]), "r"(b[1]));
}

__global__ __launch_bounds__(256) void gemm_mma(
    const float* __restrict__ bq, const float* __restrict__ bk,
    const float* __restrict__ bv, const float* __restrict__ bs,
    int M)
{
    // [stage][array: Ah,Al,Bh,Bl][128 rows * APAD16]
    __shared__ __nv_bfloat16 sm[2][4][128 * APAD16];   // 48 KB exactly

    const float* bias;
    switch (blockIdx.y) {
        case 0:  bias = bq; break;
        case 1:  bias = bk; break;
        case 2:  bias = bv; break;
        default: bias = bs; break;
    }
    const bool to_half = (blockIdx.y == 1) || (blockIdx.y == 2);
    float* outf = (blockIdx.y == 0) ? g_q : g_skip;
    const int hsub = (blockIdx.y == 1) ? 0 : 4;

    const int tid  = threadIdx.x;
    const int wid  = tid >> 5;
    const int lane = tid & 31;
    const int wm   = wid >> 2;
    const int wn   = wid & 3;
    const int m0   = blockIdx.x * 128;
    const int nb0  = blockIdx.y * 128;     // W row block
    const int qrow = lane >> 2;
    const int qk   = (lane & 3) * 2;

    // per-thread cp.async coordinates: 256 chunks of 16B per array per tile
    const int lr = tid >> 1;               // 0..127 row
    const int lc = tid & 1;                // 0..1 chunk within 32B row
    const uint32_t so = (uint32_t)(lr * APAD16 + lc * 8) * 2;   // smem byte offset
    const size_t gaA = (size_t)(m0 + lr) * FDIM + lc * 8;       // in halves (+kt later)
    const size_t gaB = (size_t)(nb0 + lr) * FDIM + lc * 8;
    const uint32_t sb = smem_u32(&sm[0][0][0]);
    const uint32_t SA = 128 * APAD16 * 2;          // bytes per array
    const uint32_t SS = 4 * SA;                    // bytes per stage

    float c[4][4][4];
    #pragma unroll
    for (int mi = 0; mi < 4; mi++)
        #pragma unroll
        for (int nj = 0; nj < 4; nj++)
            #pragma unroll
            for (int r = 0; r < 4; r++) c[mi][nj][r] = 0.f;

    // prologue: load tile 0 into stage 0
    {
        const int kt = 0;
        cp16(sb + 0 * SS + 0 * SA + so, g_xh + gaA + kt);
        cp16(sb + 0 * SS + 1 * SA + so, g_xl + gaA + kt);
        cp16(sb + 0 * SS + 2 * SA + so, g_wh + gaB + kt);
        cp16(sb + 0 * SS + 3 * SA + so, g_wl + gaB + kt);
        asm volatile("cp.async.commit_group;");
    }

    for (int ct = 0; ct < NTILE; ct++) {
        const int s = ct & 1;
        if (ct + 1 < NTILE) {
            const int kt = (ct + 1) * 16;
            const uint32_t st = ((ct + 1) & 1) * SS;
            cp16(sb + st + 0 * SA + so, g_xh + gaA + kt);
            cp16(sb + st + 1 * SA + so, g_xl + gaA + kt);
            cp16(sb + st + 2 * SA + so, g_wh + gaB + kt);
            cp16(sb + st + 3 * SA + so, g_wl + gaB + kt);
            asm volatile("cp.async.commit_group;");
            asm volatile("cp.async.wait_group 1;");
        } else {
            asm volatile("cp.async.wait_group 0;");
        }
        __syncthreads();

        #pragma unroll
        for (int pass = 0; pass < 3; pass++) {
            const __nv_bfloat16* Ab = sm[s][(pass == 1) ? 1 : 0];
            const __nv_bfloat16* Bb = sm[s][(pass == 2) ? 3 : 2];
            uint32_t a[4][4], b[4][2];
            #pragma unroll
            for (int mi = 0; mi < 4; mi++) {
                const int row = wm * 64 + mi * 16 + qrow;
                a[mi][0] = *(const uint32_t*)(Ab + row * APAD16 + qk);
                a[mi][1] = *(const uint32_t*)(Ab + (row + 8) * APAD16 + qk);
                a[mi][2] = *(const uint32_t*)(Ab + row * APAD16 + qk + 8);
                a[mi][3] = *(const uint32_t*)(Ab + (row + 8) * APAD16 + qk + 8);
            }
            #pragma unroll
            for (int nj = 0; nj < 4; nj++) {
                const int col = wn * 32 + nj * 8 + qrow;
                b[nj][0] = *(const uint32_t*)(Bb + col * APAD16 + qk);
                b[nj][1] = *(const uint32_t*)(Bb + col * APAD16 + qk + 8);
            }
            #pragma unroll
            for (int mi = 0; mi < 4; mi++)
                #pragma unroll
                for (int nj = 0; nj < 4; nj++)
                    mma_bf16(c[mi][nj], a[mi], b[nj]);
        }
        __syncthreads();
    }

    float2 bj[4];
    #pragma unroll
    for (int nj = 0; nj < 4; nj++) {
        const int col = wn * 32 + nj * 8 + (lane & 3) * 2;
        bj[nj] = *(const float2*)(bias + col);
    }
    #pragma unroll
    for (int mi = 0; mi < 4; mi++) {
        const int r0 = m0 + wm * 64 + mi * 16 + qrow;
        #pragma unroll
        for (int nj = 0; nj < 4; nj++) {
            const int col = wn * 32 + nj * 8 + (lane & 3) * 2;
            const float v00 = c[mi][nj][0] + bj[nj].x;
            const float v01 = c[mi][nj][1] + bj[nj].y;
            const float v10 = c[mi][nj][2] + bj[nj].x;
            const float v11 = c[mi][nj][3] + bj[nj].y;
            if (to_half) {
                const int off = ((col >> 2) << 3) + (col & 3) + hsub;
                if (r0 < M)
                    *(__half2*)(g_kv + (size_t)r0 * 256 + off) = __floats2half2_rn(v00, v01);
                if (r0 + 8 < M)
                    *(__half2*)(g_kv + (size_t)(r0 + 8) * 256 + off) = __floats2half2_rn(v10, v11);
            } else {
                if (r0 < M)
                    *(float2*)(outf + (size_t)r0 * 128 + col) = make_float2(v00, v01);
                if (r0 + 8 < M)
                    *(float2*)(outf + (size_t)(r0 + 8) * 128 + col) = make_float2(v10, v11);
            }
        }
    }
}

// ---------------- 2) CSR build ----------------
__global__ void zero_counts(int n)
{
    int i = blockIdx.x * blockDim.x + threadIdx.x;
    if (i < n) g_count[i] = 0;
}

__global__ void hist_kernel(const int* __restrict__ ei, int e)
{
    int i = blockIdx.x * blockDim.x + threadIdx.x;
    if (i < e) atomicAdd(&g_count[ei[e + i]], 1);
}

__global__ void scan_blocks(int n)
{
    __shared__ int sh[SCAN_BLK];
    const int t = threadIdx.x;
    const int i = blockIdx.x * SCAN_BLK + t;
    const int v = (i < n) ? g_count[i] : 0;
    sh[t] = v;
    __syncthreads();
    #pragma unroll
    for (int off = 1; off < SCAN_BLK; off <<= 1) {
        int u = (t >= off) ? sh[t - off] : 0;
        __syncthreads();
        sh[t] += u;
        __syncthreads();
    }
    if (i < n) g_rowptr[i] = sh[t] - v;
    if (t == SCAN_BLK - 1) g_bsum[blockIdx.x] = sh[t];
}

__global__ void scan_tops(int nb, int n)
{
    __shared__ int sh[SCAN_BLK];
    const int t = threadIdx.x;
    const int v = (t < nb) ? g_bsum[t] : 0;
    sh[t] = v;
    __syncthreads();
    #pragma unroll
    for (int off = 1; off < SCAN_BLK; off <<= 1) {
        int u = (t >= off) ? sh[t - off] : 0;
        __syncthreads();
        sh[t] += u;
        __syncthreads();
    }
    g_boff[t] = sh[t] - v;
    if (t == SCAN_BLK - 1) g_rowptr[n] = sh[t];
}

__global__ void add_offsets(int n)
{
    const int i = blockIdx.x * blockDim.x + threadIdx.x;
    if (i < n) {
        const int r = g_rowptr[i] + g_boff[i / SCAN_BLK];
        g_rowptr[i] = r;
        g_fill[i]   = r;
    }
}

__global__ void scatter_kernel(const int* __restrict__ ei, int e)
{
    int i = blockIdx.x * blockDim.x + threadIdx.x;
    if (i < e) {
        int dst  = ei[e + i];
        int slot = atomicAdd(&g_fill[dst], 1);
        g_esrc[slot] = ei[i];
    }
}

// ---------------- 3) fused attention aggregation (warp per dst node) ----------------
__global__ __launch_bounds__(256) void edge_attn(float* __restrict__ out, int n)
{
    const int warp = (blockIdx.x * blockDim.x + threadIdx.x) >> 5;
    const int lane = threadIdx.x & 31;
    if (warp >= n) return;
    const int node = warp;

    const float scale = 0.17677669529663687f;  // 1/sqrt(32)
    float4 q4 = *(const float4*)(g_q + (size_t)node * 128 + lane * 4);
    q4.x *= scale; q4.y *= scale; q4.z *= scale; q4.w *= scale;

    float4 acc = make_float4(0.f, 0.f, 0.f, 0.f);
    float den = 0.f;

    const int beg = g_rowptr[node];
    const int end = g_rowptr[node + 1];

    int i = beg;
    for (; i + 2 <= end; i += 2) {
        const int s0 = __ldg(&g_esrc[i]);
        const int s1 = __ldg(&g_esrc[i + 1]);
        const uint4 kv0 = *(const uint4*)(g_kv + (size_t)s0 * 256 + lane * 8);
        const uint4 kv1 = *(const uint4*)(g_kv + (size_t)s1 * 256 + lane * 8);
        const float2 k0a = __half22float2(*(const __half2*)&kv0.x);
        const float2 k0b = __half22float2(*(const __half2*)&kv0.y);
        const float2 k1a = __half22float2(*(const __half2*)&kv1.x);
        const float2 k1b = __half22float2(*(const __half2*)&kv1.y);
        float p0 = q4.x * k0a.x + q4.y * k0a.y + q4.z * k0b.x + q4.w * k0b.y;
        float p1 = q4.x * k1a.x + q4.y * k1a.y + q4.z * k1b.x + q4.w * k1b.y;
        p0 += __shfl_xor_sync(0xffffffffu, p0, 1, 8);
        p1 += __shfl_xor_sync(0xffffffffu, p1, 1, 8);
        p0 += __shfl_xor_sync(0xffffffffu, p0, 2, 8);
        p1 += __shfl_xor_sync(0xffffffffu, p1, 2, 8);
        p0 += __shfl_xor_sync(0xffffffffu, p0, 4, 8);
        p1 += __shfl_xor_sync(0xffffffffu, p1, 4, 8);
        const float w0 = __expf(p0);
        const float w1 = __expf(p1);
        const float2 v0a = __half22float2(*(const __half2*)&kv0.z);
        const float2 v0b = __half22float2(*(const __half2*)&kv0.w);
        const float2 v1a = __half22float2(*(const __half2*)&kv1.z);
        const float2 v1b = __half22float2(*(const __half2*)&kv1.w);
        den += w0 + w1;
        acc.x = fmaf(w0, v0a.x, fmaf(w1, v1a.x, acc.x));
        acc.y = fmaf(w0, v0a.y, fmaf(w1, v1a.y, acc.y));
        acc.z = fmaf(w0, v0b.x, fmaf(w1, v1b.x, acc.z));
        acc.w = fmaf(w0, v0b.y, fmaf(w1, v1b.y, acc.w));
    }
    if (i < end) {
        const int s0 = __ldg(&g_esrc[i]);
        const uint4 kv0 = *(const uint4*)(g_kv + (size_t)s0 * 256 + lane * 8);
        const float2 k0a = __half22float2(*(const __half2*)&kv0.x);
        const float2 k0b = __half22float2(*(const __half2*)&kv0.y);
        float p0 = q4.x * k0a.x + q4.y * k0a.y + q4.z * k0b.x + q4.w * k0b.y;
        p0 += __shfl_xor_sync(0xffffffffu, p0, 1, 8);
        p0 += __shfl_xor_sync(0xffffffffu, p0, 2, 8);
        p0 += __shfl_xor_sync(0xffffffffu, p0, 4, 8);
        const float w0 = __expf(p0);
        const float2 v0a = __half22float2(*(const __half2*)&kv0.z);
        const float2 v0b = __half22float2(*(const __half2*)&kv0.w);
        den += w0;
        acc.x = fmaf(w0, v0a.x, acc.x);
        acc.y = fmaf(w0, v0a.y, acc.y);
        acc.z = fmaf(w0, v0b.x, acc.z);
        acc.w = fmaf(w0, v0b.y, acc.w);
    }

    const float inv = (den > 0.f) ? (1.0f / den) : 0.f;
    const float4 sk = *(const float4*)(g_skip + (size_t)node * 128 + lane * 4);
    float4 o;
    o.x = fmaxf(fmaf(acc.x, inv, sk.x), 0.f);
    o.y = fmaxf(fmaf(acc.y, inv, sk.y), 0.f);
    o.z = fmaxf(fmaf(acc.z, inv, sk.z), 0.f);
    o.w = fmaxf(fmaf(acc.w, inv, sk.w), 0.f);
    *(float4*)(out + (size_t)node * 128 + lane * 4) = o;
}

// ---------------- host launcher ----------------
extern "C" void kernel_launch(void* const* d_in, const int* in_sizes, int n_in,
                              void* d_out, int out_size)
{
    const float* x  = (const float*)d_in[0];
    const int*   ei = (const int*)  d_in[1];
    const float* Wq = (const float*)d_in[2];
    const float* bq = (const float*)d_in[3];
    const float* Wk = (const float*)d_in[4];
    const float* bk = (const float*)d_in[5];
    const float* Wv = (const float*)d_in[6];
    const float* bv = (const float*)d_in[7];
    const float* Ws = (const float*)d_in[8];
    const float* bs = (const float*)d_in[9];
    float* out = (float*)d_out;

    const int n = in_sizes[0] / FDIM;   // 50000
    const int e = in_sizes[1] / 2;      // 800000
    const int nb = (n + SCAN_BLK - 1) / SCAN_BLK;

    // Side stream: CSR build overlaps split + GEMM.
    cudaStream_t s2;
    cudaEvent_t ev0, ev1;
    cudaStreamCreateWithFlags(&s2, cudaStreamNonBlocking);
    cudaEventCreateWithFlags(&ev0, cudaEventDisableTiming);
    cudaEventCreateWithFlags(&ev1, cudaEventDisableTiming);

    cudaEventRecord(ev0, 0);
    cudaStreamWaitEvent(s2, ev0, 0);

    zero_counts<<<(n + 255) / 256, 256, 0, s2>>>(n);
    hist_kernel<<<(e + 255) / 256, 256, 0, s2>>>(ei, e);
    scan_blocks<<<nb, SCAN_BLK, 0, s2>>>(n);
    scan_tops<<<1, SCAN_BLK, 0, s2>>>(nb, n);
    add_offsets<<<(n + 255) / 256, 256, 0, s2>>>(n);
    scatter_kernel<<<(e + 255) / 256, 256, 0, s2>>>(ei, e);
    cudaEventRecord(ev1, s2);

    // operand split, then pipelined GEMM, on main stream
    split_x<<<(n * (FDIM / 4) + 255) / 256, 256>>>(x, n);
    split_w<<<(512 * (FDIM / 4) + 255) / 256, 256>>>(Wq, Wk, Wv, Ws);
    dim3 gg((n + 127) / 128, 4);
    gemm_mma<<<gg, 256>>>(bq, bk, bv, bs, n);

    cudaStreamWaitEvent(0, ev1, 0);
    edge_attn<<<(n * 32 + 255) / 256, 256>>>(out, n);
}

// round 10
// speedup vs baseline: 1.1818x; 1.0571x over previous
#include <cuda_runtime.h>
#include <cuda_bf16.h>
#include <cuda_fp16.h>
#include <math.h>
#include <stdint.h>

// Problem constants
#define NMAX 50000
#define EMAX 800000
#define FDIM 128
#define SCAN_BLK 512
#define MPAD 128   // row padding so cp.async can safely over-read the last tile

// ---------------- device scratch ----------------
__device__ float  g_q[NMAX * FDIM];
__device__ float  g_skip[NMAX * FDIM];
// Interleaved kv: per node 256 halves; lane-l group at l*8: [k(4l..4l+3) | v(4l..4l+3)]
__device__ __half g_kv[NMAX * 256];
// Pre-split fp16 operands: x = hi + lo, W single fp16
__device__ __half g_xh[(NMAX + MPAD) * FDIM];
__device__ __half g_xl[(NMAX + MPAD) * FDIM];
__device__ __half g_wh[512 * FDIM];
__device__ int    g_count[NMAX];
__device__ int    g_rowptr[NMAX + 1];
__device__ int    g_fill[NMAX];
__device__ int    g_esrc[EMAX];
__device__ int    g_bsum[1024];
__device__ int    g_boff[1024];

// ---------------- helpers ----------------
__device__ __forceinline__ uint32_t smem_u32(const void* p) {
    uint32_t a;
    asm("{ .reg .u64 t; cvta.to.shared.u64 t, %1; cvt.u32.u64 %0, t; }" : "=r"(a) : "l"(p));
    return a;
}
__device__ __forceinline__ void cp16(uint32_t dst, const void* src) {
    asm volatile("cp.async.cg.shared.global [%0], [%1], 16;" :: "r"(dst), "l"(src));
}

// ---------------- 0) split x (fp16 hi+lo) and W (fp16) ----------------
__global__ void split_all(const float* __restrict__ x,
                          const float* __restrict__ Wq, const float* __restrict__ Wk,
                          const float* __restrict__ Wv, const float* __restrict__ Ws,
                          int n)
{
    const int nx = n * (FDIM / 4);
    const int i = blockIdx.x * blockDim.x + threadIdx.x;
    if (i < nx) {
        float4 v = *(const float4*)(x + (size_t)i * 4);
        __half hx = __float2half_rn(v.x);
        __half hy = __float2half_rn(v.y);
        __half hz = __float2half_rn(v.z);
        __half hw = __float2half_rn(v.w);
        ushort4 h4, l4;
        h4.x = __half_as_ushort(hx); l4.x = __half_as_ushort(__float2half_rn(v.x - __half2float(hx)));
        h4.y = __half_as_ushort(hy); l4.y = __half_as_ushort(__float2half_rn(v.y - __half2float(hy)));
        h4.z = __half_as_ushort(hz); l4.z = __half_as_ushort(__float2half_rn(v.z - __half2float(hz)));
        h4.w = __half_as_ushort(hw); l4.w = __half_as_ushort(__float2half_rn(v.w - __half2float(hw)));
        *(ushort4*)(g_xh + (size_t)i * 4) = h4;
        *(ushort4*)(g_xl + (size_t)i * 4) = l4;
    } else {
        const int j = i - nx;                 // over 512*32 float4s
        if (j >= 512 * (FDIM / 4)) return;
        const int m = j >> 12;
        const int r = j & 4095;
        const float* W = (m == 0) ? Wq : (m == 1) ? Wk : (m == 2) ? Wv : Ws;
        float4 v = *(const float4*)(W + (size_t)r * 4);
        ushort4 h4;
        h4.x = __half_as_ushort(__float2half_rn(v.x));
        h4.y = __half_as_ushort(__float2half_rn(v.y));
        h4.z = __half_as_ushort(__float2half_rn(v.z));
        h4.w = __half_as_ushort(__float2half_rn(v.w));
        *(ushort4*)(g_wh + (size_t)j * 4) = h4;
    }
}

// ---------------- 1) cp.async-pipelined fp16 mma GEMM (2 passes) ----------------
#define APAD16 24
#define NTILE  8    // 128 / 16

__device__ __forceinline__ void mma_fp16(float c[4], const uint32_t a[4], const uint32_t b[2]) {
    asm volatile(
        "mma.sync.aligned.m16n8k16.row.col.f32.f16.f16.f32 "
        "{%0,%1,%2,%3}, {%4,%5,%6,%7}, {%8,%9}, {%0,%1,%2,%3};"
        : "+f"(c[0]), "+f"(c[1]), "+f"(c[2]), "+f"(c[3])
        : "r"(a[0]), "r"(a[1]), "r"(a[2]), "r"(a[3]), "r"(b[0]), "r"(b[1]));
}

__global__ __launch_bounds__(256) void gemm_mma(
    const float* __restrict__ bq, const float* __restrict__ bk,
    const float* __restrict__ bv, const float* __restrict__ bs,
    int M)
{
    // [stage][array: Ah,Al,B][128 rows * APAD16]  = 36 KB
    __shared__ __half sm[2][3][128 * APAD16];

    const float* bias;
    switch (blockIdx.y) {
        case 0:  bias = bq; break;
        case 1:  bias = bk; break;
        case 2:  bias = bv; break;
        default: bias = bs; break;
    }
    const bool to_half = (blockIdx.y == 1) || (blockIdx.y == 2);
    float* outf = (blockIdx.y == 0) ? g_q : g_skip;
    const int hsub = (blockIdx.y == 1) ? 0 : 4;

    const int tid  = threadIdx.x;
    const int wid  = tid >> 5;
    const int lane = tid & 31;
    const int wm   = wid >> 2;
    const int wn   = wid & 3;
    const int m0   = blockIdx.x * 128;
    const int nb0  = blockIdx.y * 128;     // W row block
    const int qrow = lane >> 2;
    const int qk   = (lane & 3) * 2;

    // per-thread cp.async coordinates: 256 chunks of 16B per array per tile
    const int lr = tid >> 1;               // 0..127 row
    const int lc = tid & 1;                // 0..1 chunk within 32B row
    const uint32_t so = (uint32_t)(lr * APAD16 + lc * 8) * 2;   // smem byte offset
    const size_t gaA = (size_t)(m0 + lr) * FDIM + lc * 8;       // halves (+kt later)
    const size_t gaB = (size_t)(nb0 + lr) * FDIM + lc * 8;
    const uint32_t sb = smem_u32(&sm[0][0][0]);
    const uint32_t SA = 128 * APAD16 * 2;          // bytes per array
    const uint32_t SS = 3 * SA;                    // bytes per stage

    float c[4][4][4];
    #pragma unroll
    for (int mi = 0; mi < 4; mi++)
        #pragma unroll
        for (int nj = 0; nj < 4; nj++)
            #pragma unroll
            for (int r = 0; r < 4; r++) c[mi][nj][r] = 0.f;

    // prologue: tile 0 -> stage 0
    {
        cp16(sb + 0 * SS + 0 * SA + so, g_xh + gaA);
        cp16(sb + 0 * SS + 1 * SA + so, g_xl + gaA);
        cp16(sb + 0 * SS + 2 * SA + so, g_wh + gaB);
        asm volatile("cp.async.commit_group;");
    }

    for (int ct = 0; ct < NTILE; ct++) {
        const int s = ct & 1;
        if (ct + 1 < NTILE) {
            const int kt = (ct + 1) * 16;
            const uint32_t st = ((ct + 1) & 1) * SS;
            cp16(sb + st + 0 * SA + so, g_xh + gaA + kt);
            cp16(sb + st + 1 * SA + so, g_xl + gaA + kt);
            cp16(sb + st + 2 * SA + so, g_wh + gaB + kt);
            asm volatile("cp.async.commit_group;");
            asm volatile("cp.async.wait_group 1;");
        } else {
            asm volatile("cp.async.wait_group 0;");
        }
        __syncthreads();

        #pragma unroll
        for (int pass = 0; pass < 2; pass++) {
            const __half* Ab = sm[s][pass];
            const __half* Bb = sm[s][2];
            uint32_t a[4][4], b[4][2];
            #pragma unroll
            for (int mi = 0; mi < 4; mi++) {
                const int row = wm * 64 + mi * 16 + qrow;
                a[mi][0] = *(const uint32_t*)(Ab + row * APAD16 + qk);
                a[mi][1] = *(const uint32_t*)(Ab + (row + 8) * APAD16 + qk);
                a[mi][2] = *(const uint32_t*)(Ab + row * APAD16 + qk + 8);
                a[mi][3] = *(const uint32_t*)(Ab + (row + 8) * APAD16 + qk + 8);
            }
            #pragma unroll
            for (int nj = 0; nj < 4; nj++) {
                const int col = wn * 32 + nj * 8 + qrow;
                b[nj][0] = *(const uint32_t*)(Bb + col * APAD16 + qk);
                b[nj][1] = *(const uint32_t*)(Bb + col * APAD16 + qk + 8);
            }
            #pragma unroll
            for (int mi = 0; mi < 4; mi++)
                #pragma unroll
                for (int nj = 0; nj < 4; nj++)
                    mma_fp16(c[mi][nj], a[mi], b[nj]);
        }
        __syncthreads();
    }

    float2 bj[4];
    #pragma unroll
    for (int nj = 0; nj < 4; nj++) {
        const int col = wn * 32 + nj * 8 + (lane & 3) * 2;
        bj[nj] = *(const float2*)(bias + col);
    }
    #pragma unroll
    for (int mi = 0; mi < 4; mi++) {
        const int r0 = m0 + wm * 64 + mi * 16 + qrow;
        #pragma unroll
        for (int nj = 0; nj < 4; nj++) {
            const int col = wn * 32 + nj * 8 + (lane & 3) * 2;
            const float v00 = c[mi][nj][0] + bj[nj].x;
            const float v01 = c[mi][nj][1] + bj[nj].y;
            const float v10 = c[mi][nj][2] + bj[nj].x;
            const float v11 = c[mi][nj][3] + bj[nj].y;
            if (to_half) {
                const int off = ((col >> 2) << 3) + (col & 3) + hsub;
                if (r0 < M)
                    *(__half2*)(g_kv + (size_t)r0 * 256 + off) = __floats2half2_rn(v00, v01);
                if (r0 + 8 < M)
                    *(__half2*)(g_kv + (size_t)(r0 + 8) * 256 + off) = __floats2half2_rn(v10, v11);
            } else {
                if (r0 < M)
                    *(float2*)(outf + (size_t)r0 * 128 + col) = make_float2(v00, v01);
                if (r0 + 8 < M)
                    *(float2*)(outf + (size_t)(r0 + 8) * 128 + col) = make_float2(v10, v11);
            }
        }
    }
}

// ---------------- 2) CSR build ----------------
__global__ void zero_counts(int n)
{
    int i = blockIdx.x * blockDim.x + threadIdx.x;
    if (i < n) g_count[i] = 0;
}

__global__ void hist_kernel(const int* __restrict__ ei, int e)
{
    int i = blockIdx.x * blockDim.x + threadIdx.x;
    if (i < e) atomicAdd(&g_count[ei[e + i]], 1);
}

__global__ void scan_blocks(int n)
{
    __shared__ int sh[SCAN_BLK];
    const int t = threadIdx.x;
    const int i = blockIdx.x * SCAN_BLK + t;
    const int v = (i < n) ? g_count[i] : 0;
    sh[t] = v;
    __syncthreads();
    #pragma unroll
    for (int off = 1; off < SCAN_BLK; off <<= 1) {
        int u = (t >= off) ? sh[t - off] : 0;
        __syncthreads();
        sh[t] += u;
        __syncthreads();
    }
    if (i < n) g_rowptr[i] = sh[t] - v;
    if (t == SCAN_BLK - 1) g_bsum[blockIdx.x] = sh[t];
}

__global__ void scan_tops(int nb, int n)
{
    __shared__ int sh[SCAN_BLK];
    const int t = threadIdx.x;
    const int v = (t < nb) ? g_bsum[t] : 0;
    sh[t] = v;
    __syncthreads();
    #pragma unroll
    for (int off = 1; off < SCAN_BLK; off <<= 1) {
        int u = (t >= off) ? sh[t - off] : 0;
        __syncthreads();
        sh[t] += u;
        __syncthreads();
    }
    g_boff[t] = sh[t] - v;
    if (t == SCAN_BLK - 1) g_rowptr[n] = sh[t];
}

__global__ void add_offsets(int n)
{
    const int i = blockIdx.x * blockDim.x + threadIdx.x;
    if (i < n) {
        const int r = g_rowptr[i] + g_boff[i / SCAN_BLK];
        g_rowptr[i] = r;
        g_fill[i]   = r;
    }
}

__global__ void scatter_kernel(const int* __restrict__ ei, int e)
{
    int i = blockIdx.x * blockDim.x + threadIdx.x;
    if (i < e) {
        int dst  = ei[e + i];
        int slot = atomicAdd(&g_fill[dst], 1);
        g_esrc[slot] = ei[i];
    }
}

// ---------------- 3) fused attention aggregation (warp per dst node) ----------------
// One LDG.128 per edge per lane (interleaved kv); 4-edge unroll for MLP.
__global__ __launch_bounds__(256) void edge_attn(float* __restrict__ out, int n)
{
    const int warp = (blockIdx.x * blockDim.x + threadIdx.x) >> 5;
    const int lane = threadIdx.x & 31;
    if (warp >= n) return;
    const int node = warp;

    const float scale = 0.17677669529663687f;  // 1/sqrt(32)
    float4 q4 = *(const float4*)(g_q + (size_t)node * 128 + lane * 4);
    q4.x *= scale; q4.y *= scale; q4.z *= scale; q4.w *= scale;

    float4 acc = make_float4(0.f, 0.f, 0.f, 0.f);
    float den = 0.f;

    const int beg = g_rowptr[node];
    const int end = g_rowptr[node + 1];

    int i = beg;
    for (; i + 4 <= end; i += 4) {
        int s[4];
        uint4 kv[4];
        #pragma unroll
        for (int u = 0; u < 4; u++) s[u] = __ldg(&g_esrc[i + u]);
        #pragma unroll
        for (int u = 0; u < 4; u++)
            kv[u] = *(const uint4*)(g_kv + (size_t)s[u] * 256 + lane * 8);

        float p[4];
        #pragma unroll
        for (int u = 0; u < 4; u++) {
            const float2 ka = __half22float2(*(const __half2*)&kv[u].x);
            const float2 kb = __half22float2(*(const __half2*)&kv[u].y);
            p[u] = q4.x * ka.x + q4.y * ka.y + q4.z * kb.x + q4.w * kb.y;
        }
        #pragma unroll
        for (int u = 0; u < 4; u++) p[u] += __shfl_xor_sync(0xffffffffu, p[u], 1, 8);
        #pragma unroll
        for (int u = 0; u < 4; u++) p[u] += __shfl_xor_sync(0xffffffffu, p[u], 2, 8);
        #pragma unroll
        for (int u = 0; u < 4; u++) p[u] += __shfl_xor_sync(0xffffffffu, p[u], 4, 8);

        #pragma unroll
        for (int u = 0; u < 4; u++) {
            const float w = __expf(p[u]);
            const float2 va = __half22float2(*(const __half2*)&kv[u].z);
            const float2 vb = __half22float2(*(const __half2*)&kv[u].w);
            den += w;
            acc.x = fmaf(w, va.x, acc.x);
            acc.y = fmaf(w, va.y, acc.y);
            acc.z = fmaf(w, vb.x, acc.z);
            acc.w = fmaf(w, vb.y, acc.w);
        }
    }
    for (; i < end; i++) {
        const int s0 = __ldg(&g_esrc[i]);
        const uint4 kv0 = *(const uint4*)(g_kv + (size_t)s0 * 256 + lane * 8);
        const float2 ka = __half22float2(*(const __half2*)&kv0.x);
        const float2 kb = __half22float2(*(const __half2*)&kv0.y);
        float p0 = q4.x * ka.x + q4.y * ka.y + q4.z * kb.x + q4.w * kb.y;
        p0 += __shfl_xor_sync(0xffffffffu, p0, 1, 8);
        p0 += __shfl_xor_sync(0xffffffffu, p0, 2, 8);
        p0 += __shfl_xor_sync(0xffffffffu, p0, 4, 8);
        const float w = __expf(p0);
        const float2 va = __half22float2(*(const __half2*)&kv0.z);
        const float2 vb = __half22float2(*(const __half2*)&kv0.w);
        den += w;
        acc.x = fmaf(w, va.x, acc.x);
        acc.y = fmaf(w, va.y, acc.y);
        acc.z = fmaf(w, vb.x, acc.z);
        acc.w = fmaf(w, vb.y, acc.w);
    }

    const float inv = (den > 0.f) ? (1.0f / den) : 0.f;
    const float4 sk = *(const float4*)(g_skip + (size_t)node * 128 + lane * 4);
    float4 o;
    o.x = fmaxf(fmaf(acc.x, inv, sk.x), 0.f);
    o.y = fmaxf(fmaf(acc.y, inv, sk.y), 0.f);
    o.z = fmaxf(fmaf(acc.z, inv, sk.z), 0.f);
    o.w = fmaxf(fmaf(acc.w, inv, sk.w), 0.f);
    *(float4*)(out + (size_t)node * 128 + lane * 4) = o;
}

// ---------------- host launcher ----------------
extern "C" void kernel_launch(void* const* d_in, const int* in_sizes, int n_in,
                              void* d_out, int out_size)
{
    const float* x  = (const float*)d_in[0];
    const int*   ei = (const int*)  d_in[1];
    const float* Wq = (const float*)d_in[2];
    const float* bq = (const float*)d_in[3];
    const float* Wk = (const float*)d_in[4];
    const float* bk = (const float*)d_in[5];
    const float* Wv = (const float*)d_in[6];
    const float* bv = (const float*)d_in[7];
    const float* Ws = (const float*)d_in[8];
    const float* bs = (const float*)d_in[9];
    float* out = (float*)d_out;

    const int n = in_sizes[0] / FDIM;   // 50000
    const int e = in_sizes[1] / 2;      // 800000
    const int nb = (n + SCAN_BLK - 1) / SCAN_BLK;

    // Side stream: CSR build overlaps split + GEMM.
    cudaStream_t s2;
    cudaEvent_t ev0, ev1;
    cudaStreamCreateWithFlags(&s2, cudaStreamNonBlocking);
    cudaEventCreateWithFlags(&ev0, cudaEventDisableTiming);
    cudaEventCreateWithFlags(&ev1, cudaEventDisableTiming);

    cudaEventRecord(ev0, 0);
    cudaStreamWaitEvent(s2, ev0, 0);

    zero_counts<<<(n + 255) / 256, 256, 0, s2>>>(n);
    hist_kernel<<<(e + 255) / 256, 256, 0, s2>>>(ei, e);
    scan_blocks<<<nb, SCAN_BLK, 0, s2>>>(n);
    scan_tops<<<1, SCAN_BLK, 0, s2>>>(nb, n);
    add_offsets<<<(n + 255) / 256, 256, 0, s2>>>(n);
    scatter_kernel<<<(e + 255) / 256, 256, 0, s2>>>(ei, e);
    cudaEventRecord(ev1, s2);

    // operand split, then pipelined GEMM, on main stream
    const int tot4 = n * (FDIM / 4) + 512 * (FDIM / 4);
    split_all<<<(tot4 + 255) / 256, 256>>>(x, Wq, Wk, Wv, Ws, n);
    dim3 gg((n + 127) / 128, 4);
    gemm_mma<<<gg, 256>>>(bq, bk, bv, bs, n);

    cudaStreamWaitEvent(0, ev1, 0);
    edge_attn<<<(n * 32 + 255) / 256, 256>>>(out, n);
}

// round 11
// speedup vs baseline: 1.2116x; 1.0252x over previous
#include <cuda_runtime.h>
#include <cuda_bf16.h>
#include <cuda_fp16.h>
#include <math.h>
#include <stdint.h>

// Problem constants
#define NMAX 50000
#define EMAX 800000
#define FDIM 128
#define SCAN_BLK 512
#define MPAD 128   // row padding so cp.async can safely over-read the last tile

// ---------------- device scratch ----------------
__device__ float  g_q[NMAX * FDIM];
__device__ float  g_skip[NMAX * FDIM];
// Interleaved kv: per node 256 halves; lane-l group at l*8: [k(4l..4l+3) | v(4l..4l+3)]
__device__ __half g_kv[NMAX * 256];
// Pre-split fp16 operands: x = hi + lo, W single fp16
__device__ __half g_xh[(NMAX + MPAD) * FDIM];
__device__ __half g_xl[(NMAX + MPAD) * FDIM];
__device__ __half g_wh[512 * FDIM];
__device__ int    g_count[NMAX];
__device__ int    g_rowptr[NMAX + 1];
__device__ int    g_fill[NMAX];
__device__ int    g_esrc[EMAX];
__device__ int    g_bsum[1024];
__device__ int    g_boff[1024];

// ---------------- helpers ----------------
__device__ __forceinline__ uint32_t smem_u32(const void* p) {
    uint32_t a;
    asm("{ .reg .u64 t; cvta.to.shared.u64 t, %1; cvt.u32.u64 %0, t; }" : "=r"(a) : "l"(p));
    return a;
}
__device__ __forceinline__ void cp16(uint32_t dst, const void* src) {
    asm volatile("cp.async.cg.shared.global [%0], [%1], 16;" :: "r"(dst), "l"(src));
}

// ---------------- 0) split x (fp16 hi+lo) and W (fp16) ----------------
__global__ void split_all(const float* __restrict__ x,
                          const float* __restrict__ Wq, const float* __restrict__ Wk,
                          const float* __restrict__ Wv, const float* __restrict__ Ws,
                          int n)
{
    const int nx = n * (FDIM / 4);
    const int i = blockIdx.x * blockDim.x + threadIdx.x;
    if (i < nx) {
        float4 v = *(const float4*)(x + (size_t)i * 4);
        __half hx = __float2half_rn(v.x);
        __half hy = __float2half_rn(v.y);
        __half hz = __float2half_rn(v.z);
        __half hw = __float2half_rn(v.w);
        ushort4 h4, l4;
        h4.x = __half_as_ushort(hx); l4.x = __half_as_ushort(__float2half_rn(v.x - __half2float(hx)));
        h4.y = __half_as_ushort(hy); l4.y = __half_as_ushort(__float2half_rn(v.y - __half2float(hy)));
        h4.z = __half_as_ushort(hz); l4.z = __half_as_ushort(__float2half_rn(v.z - __half2float(hz)));
        h4.w = __half_as_ushort(hw); l4.w = __half_as_ushort(__float2half_rn(v.w - __half2float(hw)));
        *(ushort4*)(g_xh + (size_t)i * 4) = h4;
        *(ushort4*)(g_xl + (size_t)i * 4) = l4;
    } else {
        const int j = i - nx;                 // over 512*32 float4s
        if (j >= 512 * (FDIM / 4)) return;
        const int m = j >> 12;
        const int r = j & 4095;
        const float* W = (m == 0) ? Wq : (m == 1) ? Wk : (m == 2) ? Wv : Ws;
        float4 v = *(const float4*)(W + (size_t)r * 4);
        ushort4 h4;
        h4.x = __half_as_ushort(__float2half_rn(v.x));
        h4.y = __half_as_ushort(__float2half_rn(v.y));
        h4.z = __half_as_ushort(__float2half_rn(v.z));
        h4.w = __half_as_ushort(__float2half_rn(v.w));
        *(ushort4*)(g_wh + (size_t)j * 4) = h4;
    }
}

// ---------------- 1) cp.async-pipelined fp16 mma GEMM (2 passes) ----------------
#define APAD16 24
#define NTILE  8    // 128 / 16

__device__ __forceinline__ void mma_fp16(float c[4], const uint32_t a[4], const uint32_t b[2]) {
    asm volatile(
        "mma.sync.aligned.m16n8k16.row.col.f32.f16.f16.f32 "
        "{%0,%1,%2,%3}, {%4,%5,%6,%7}, {%8,%9}, {%0,%1,%2,%3};"
        : "+f"(c[0]), "+f"(c[1]), "+f"(c[2]), "+f"(c[3])
        : "r"(a[0]), "r"(a[1]), "r"(a[2]), "r"(a[3]), "r"(b[0]), "r"(b[1]));
}

__global__ __launch_bounds__(256) void gemm_mma(
    const float* __restrict__ bq, const float* __restrict__ bk,
    const float* __restrict__ bv, const float* __restrict__ bs,
    int M)
{
    // [stage][array: Ah,Al,B][128 rows * APAD16]  = 36 KB
    __shared__ __half sm[2][3][128 * APAD16];

    const float* bias;
    switch (blockIdx.y) {
        case 0:  bias = bq; break;
        case 1:  bias = bk; break;
        case 2:  bias = bv; break;
        default: bias = bs; break;
    }
    const bool to_half = (blockIdx.y == 1) || (blockIdx.y == 2);
    float* outf = (blockIdx.y == 0) ? g_q : g_skip;
    const int hsub = (blockIdx.y == 1) ? 0 : 4;

    const int tid  = threadIdx.x;
    const int wid  = tid >> 5;
    const int lane = tid & 31;
    const int wm   = wid >> 2;
    const int wn   = wid & 3;
    const int m0   = blockIdx.x * 128;
    const int nb0  = blockIdx.y * 128;     // W row block
    const int qrow = lane >> 2;
    const int qk   = (lane & 3) * 2;

    const int lr = tid >> 1;               // 0..127 row
    const int lc = tid & 1;                // 0..1 chunk within 32B row
    const uint32_t so = (uint32_t)(lr * APAD16 + lc * 8) * 2;   // smem byte offset
    const size_t gaA = (size_t)(m0 + lr) * FDIM + lc * 8;       // halves (+kt later)
    const size_t gaB = (size_t)(nb0 + lr) * FDIM + lc * 8;
    const uint32_t sb = smem_u32(&sm[0][0][0]);
    const uint32_t SA = 128 * APAD16 * 2;          // bytes per array
    const uint32_t SS = 3 * SA;                    // bytes per stage

    float c[4][4][4];
    #pragma unroll
    for (int mi = 0; mi < 4; mi++)
        #pragma unroll
        for (int nj = 0; nj < 4; nj++)
            #pragma unroll
            for (int r = 0; r < 4; r++) c[mi][nj][r] = 0.f;

    // prologue: tile 0 -> stage 0
    {
        cp16(sb + 0 * SS + 0 * SA + so, g_xh + gaA);
        cp16(sb + 0 * SS + 1 * SA + so, g_xl + gaA);
        cp16(sb + 0 * SS + 2 * SA + so, g_wh + gaB);
        asm volatile("cp.async.commit_group;");
    }

    for (int ct = 0; ct < NTILE; ct++) {
        const int s = ct & 1;
        if (ct + 1 < NTILE) {
            const int kt = (ct + 1) * 16;
            const uint32_t st = ((ct + 1) & 1) * SS;
            cp16(sb + st + 0 * SA + so, g_xh + gaA + kt);
            cp16(sb + st + 1 * SA + so, g_xl + gaA + kt);
            cp16(sb + st + 2 * SA + so, g_wh + gaB + kt);
            asm volatile("cp.async.commit_group;");
            asm volatile("cp.async.wait_group 1;");
        } else {
            asm volatile("cp.async.wait_group 0;");
        }
        __syncthreads();

        #pragma unroll
        for (int pass = 0; pass < 2; pass++) {
            const __half* Ab = sm[s][pass];
            const __half* Bb = sm[s][2];
            uint32_t a[4][4], b[4][2];
            #pragma unroll
            for (int mi = 0; mi < 4; mi++) {
                const int row = wm * 64 + mi * 16 + qrow;
                a[mi][0] = *(const uint32_t*)(Ab + row * APAD16 + qk);
                a[mi][1] = *(const uint32_t*)(Ab + (row + 8) * APAD16 + qk);
                a[mi][2] = *(const uint32_t*)(Ab + row * APAD16 + qk + 8);
                a[mi][3] = *(const uint32_t*)(Ab + (row + 8) * APAD16 + qk + 8);
            }
            #pragma unroll
            for (int nj = 0; nj < 4; nj++) {
                const int col = wn * 32 + nj * 8 + qrow;
                b[nj][0] = *(const uint32_t*)(Bb + col * APAD16 + qk);
                b[nj][1] = *(const uint32_t*)(Bb + col * APAD16 + qk + 8);
            }
            #pragma unroll
            for (int mi = 0; mi < 4; mi++)
                #pragma unroll
                for (int nj = 0; nj < 4; nj++)
                    mma_fp16(c[mi][nj], a[mi], b[nj]);
        }
        __syncthreads();
    }

    float2 bj[4];
    #pragma unroll
    for (int nj = 0; nj < 4; nj++) {
        const int col = wn * 32 + nj * 8 + (lane & 3) * 2;
        bj[nj] = *(const float2*)(bias + col);
    }
    #pragma unroll
    for (int mi = 0; mi < 4; mi++) {
        const int r0 = m0 + wm * 64 + mi * 16 + qrow;
        #pragma unroll
        for (int nj = 0; nj < 4; nj++) {
            const int col = wn * 32 + nj * 8 + (lane & 3) * 2;
            const float v00 = c[mi][nj][0] + bj[nj].x;
            const float v01 = c[mi][nj][1] + bj[nj].y;
            const float v10 = c[mi][nj][2] + bj[nj].x;
            const float v11 = c[mi][nj][3] + bj[nj].y;
            if (to_half) {
                const int off = ((col >> 2) << 3) + (col & 3) + hsub;
                if (r0 < M)
                    *(__half2*)(g_kv + (size_t)r0 * 256 + off) = __floats2half2_rn(v00, v01);
                if (r0 + 8 < M)
                    *(__half2*)(g_kv + (size_t)(r0 + 8) * 256 + off) = __floats2half2_rn(v10, v11);
            } else {
                if (r0 < M)
                    *(float2*)(outf + (size_t)r0 * 128 + col) = make_float2(v00, v01);
                if (r0 + 8 < M)
                    *(float2*)(outf + (size_t)(r0 + 8) * 128 + col) = make_float2(v10, v11);
            }
        }
    }
}

// ---------------- 2) CSR build ----------------
__global__ void zero_counts(int n)
{
    int i = blockIdx.x * blockDim.x + threadIdx.x;
    if (i < n) g_count[i] = 0;
}

__global__ void hist_kernel(const int* __restrict__ ei, int e)
{
    int i = blockIdx.x * blockDim.x + threadIdx.x;
    if (i < e) atomicAdd(&g_count[ei[e + i]], 1);
}

__global__ void scan_blocks(int n)
{
    __shared__ int sh[SCAN_BLK];
    const int t = threadIdx.x;
    const int i = blockIdx.x * SCAN_BLK + t;
    const int v = (i < n) ? g_count[i] : 0;
    sh[t] = v;
    __syncthreads();
    #pragma unroll
    for (int off = 1; off < SCAN_BLK; off <<= 1) {
        int u = (t >= off) ? sh[t - off] : 0;
        __syncthreads();
        sh[t] += u;
        __syncthreads();
    }
    if (i < n) g_rowptr[i] = sh[t] - v;
    if (t == SCAN_BLK - 1) g_bsum[blockIdx.x] = sh[t];
}

__global__ void scan_tops(int nb, int n)
{
    __shared__ int sh[SCAN_BLK];
    const int t = threadIdx.x;
    const int v = (t < nb) ? g_bsum[t] : 0;
    sh[t] = v;
    __syncthreads();
    #pragma unroll
    for (int off = 1; off < SCAN_BLK; off <<= 1) {
        int u = (t >= off) ? sh[t - off] : 0;
        __syncthreads();
        sh[t] += u;
        __syncthreads();
    }
    g_boff[t] = sh[t] - v;
    if (t == SCAN_BLK - 1) g_rowptr[n] = sh[t];
}

__global__ void add_offsets(int n)
{
    const int i = blockIdx.x * blockDim.x + threadIdx.x;
    if (i < n) {
        const int r = g_rowptr[i] + g_boff[i / SCAN_BLK];
        g_rowptr[i] = r;
        g_fill[i]   = r;
    }
}

__global__ void scatter_kernel(const int* __restrict__ ei, int e)
{
    int i = blockIdx.x * blockDim.x + threadIdx.x;
    if (i < e) {
        int dst  = ei[e + i];
        int slot = atomicAdd(&g_fill[dst], 1);
        g_esrc[slot] = ei[i];
    }
}

// ---------------- 3) fused attention aggregation: cp.async gather pipeline ----------------
// Warp per node. Groups of 4 edges double-buffered through smem via per-lane
// cp.async (each lane copies exactly the 16B it later reads -> per-thread
// wait_group is sufficient, no syncwarp needed). Edge indices software-
// pipelined one group further ahead.
#define EA_WARPS 8
__global__ __launch_bounds__(256) void edge_attn(float* __restrict__ out, int n)
{
    __shared__ char kvbuf[EA_WARPS][2][2048];   // 32 KB: 2 stages x 4 edges x 512B per warp

    const int wInB = threadIdx.x >> 5;
    const int lane = threadIdx.x & 31;
    const int node = blockIdx.x * EA_WARPS + wInB;
    if (node >= n) return;

    const float scale = 0.17677669529663687f;  // 1/sqrt(32)
    float4 q4 = *(const float4*)(g_q + (size_t)node * 128 + lane * 4);
    q4.x *= scale; q4.y *= scale; q4.z *= scale; q4.w *= scale;

    float4 acc = make_float4(0.f, 0.f, 0.f, 0.f);
    float den = 0.f;

    const int beg = g_rowptr[node];
    const int end = g_rowptr[node + 1];
    const int ngrp = (end - beg) >> 2;
    const uint32_t sbase = smem_u32(&kvbuf[wInB][0][0]);

    int sB[4];
    if (ngrp > 0) {
        int sA[4];
        #pragma unroll
        for (int u = 0; u < 4; u++) sA[u] = __ldg(&g_esrc[beg + u]);
        #pragma unroll
        for (int u = 0; u < 4; u++)
            cp16(sbase + u * 512 + lane * 16, g_kv + (size_t)sA[u] * 256 + lane * 8);
        asm volatile("cp.async.commit_group;");
        if (ngrp > 1) {
            #pragma unroll
            for (int u = 0; u < 4; u++) sB[u] = __ldg(&g_esrc[beg + 4 + u]);
        }
    }

    for (int g = 0; g < ngrp; g++) {
        if (g + 1 < ngrp) {
            const uint32_t st = sbase + ((g + 1) & 1) * 2048;
            #pragma unroll
            for (int u = 0; u < 4; u++)
                cp16(st + u * 512 + lane * 16, g_kv + (size_t)sB[u] * 256 + lane * 8);
            asm volatile("cp.async.commit_group;");
            if (g + 2 < ngrp) {
                #pragma unroll
                for (int u = 0; u < 4; u++) sB[u] = __ldg(&g_esrc[beg + (g + 2) * 4 + u]);
            }
            asm volatile("cp.async.wait_group 1;");
        } else {
            asm volatile("cp.async.wait_group 0;");
        }

        const uint32_t cur = sbase + (g & 1) * 2048;
        uint4 kv[4];
        #pragma unroll
        for (int u = 0; u < 4; u++) {
            asm("ld.shared.v4.u32 {%0,%1,%2,%3}, [%4];"
                : "=r"(kv[u].x), "=r"(kv[u].y), "=r"(kv[u].z), "=r"(kv[u].w)
                : "r"(cur + u * 512 + lane * 16));
        }
        float p[4];
        #pragma unroll
        for (int u = 0; u < 4; u++) {
            const float2 ka = __half22float2(*(const __half2*)&kv[u].x);
            const float2 kb = __half22float2(*(const __half2*)&kv[u].y);
            p[u] = q4.x * ka.x + q4.y * ka.y + q4.z * kb.x + q4.w * kb.y;
        }
        #pragma unroll
        for (int u = 0; u < 4; u++) p[u] += __shfl_xor_sync(0xffffffffu, p[u], 1, 8);
        #pragma unroll
        for (int u = 0; u < 4; u++) p[u] += __shfl_xor_sync(0xffffffffu, p[u], 2, 8);
        #pragma unroll
        for (int u = 0; u < 4; u++) p[u] += __shfl_xor_sync(0xffffffffu, p[u], 4, 8);
        #pragma unroll
        for (int u = 0; u < 4; u++) {
            const float w = __expf(p[u]);
            const float2 va = __half22float2(*(const __half2*)&kv[u].z);
            const float2 vb = __half22float2(*(const __half2*)&kv[u].w);
            den += w;
            acc.x = fmaf(w, va.x, acc.x);
            acc.y = fmaf(w, va.y, acc.y);
            acc.z = fmaf(w, vb.x, acc.z);
            acc.w = fmaf(w, vb.y, acc.w);
        }
    }

    // tail (deg % 4) via direct loads
    for (int i = beg + ngrp * 4; i < end; i++) {
        const int s0 = __ldg(&g_esrc[i]);
        const uint4 kv0 = *(const uint4*)(g_kv + (size_t)s0 * 256 + lane * 8);
        const float2 ka = __half22float2(*(const __half2*)&kv0.x);
        const float2 kb = __half22float2(*(const __half2*)&kv0.y);
        float p0 = q4.x * ka.x + q4.y * ka.y + q4.z * kb.x + q4.w * kb.y;
        p0 += __shfl_xor_sync(0xffffffffu, p0, 1, 8);
        p0 += __shfl_xor_sync(0xffffffffu, p0, 2, 8);
        p0 += __shfl_xor_sync(0xffffffffu, p0, 4, 8);
        const float w = __expf(p0);
        const float2 va = __half22float2(*(const __half2*)&kv0.z);
        const float2 vb = __half22float2(*(const __half2*)&kv0.w);
        den += w;
        acc.x = fmaf(w, va.x, acc.x);
        acc.y = fmaf(w, va.y, acc.y);
        acc.z = fmaf(w, vb.x, acc.z);
        acc.w = fmaf(w, vb.y, acc.w);
    }

    const float inv = (den > 0.f) ? (1.0f / den) : 0.f;
    const float4 sk = *(const float4*)(g_skip + (size_t)node * 128 + lane * 4);
    float4 o;
    o.x = fmaxf(fmaf(acc.x, inv, sk.x), 0.f);
    o.y = fmaxf(fmaf(acc.y, inv, sk.y), 0.f);
    o.z = fmaxf(fmaf(acc.z, inv, sk.z), 0.f);
    o.w = fmaxf(fmaf(acc.w, inv, sk.w), 0.f);
    *(float4*)(out + (size_t)node * 128 + lane * 4) = o;
}

// ---------------- host launcher ----------------
extern "C" void kernel_launch(void* const* d_in, const int* in_sizes, int n_in,
                              void* d_out, int out_size)
{
    const float* x  = (const float*)d_in[0];
    const int*   ei = (const int*)  d_in[1];
    const float* Wq = (const float*)d_in[2];
    const float* bq = (const float*)d_in[3];
    const float* Wk = (const float*)d_in[4];
    const float* bk = (const float*)d_in[5];
    const float* Wv = (const float*)d_in[6];
    const float* bv = (const float*)d_in[7];
    const float* Ws = (const float*)d_in[8];
    const float* bs = (const float*)d_in[9];
    float* out = (float*)d_out;

    const int n = in_sizes[0] / FDIM;   // 50000
    const int e = in_sizes[1] / 2;      // 800000
    const int nb = (n + SCAN_BLK - 1) / SCAN_BLK;

    // Side stream: CSR build overlaps split + GEMM.
    cudaStream_t s2;
    cudaEvent_t ev0, ev1;
    cudaStreamCreateWithFlags(&s2, cudaStreamNonBlocking);
    cudaEventCreateWithFlags(&ev0, cudaEventDisableTiming);
    cudaEventCreateWithFlags(&ev1, cudaEventDisableTiming);

    cudaEventRecord(ev0, 0);
    cudaStreamWaitEvent(s2, ev0, 0);

    zero_counts<<<(n + 255) / 256, 256, 0, s2>>>(n);
    hist_kernel<<<(e + 255) / 256, 256, 0, s2>>>(ei, e);
    scan_blocks<<<nb, SCAN_BLK, 0, s2>>>(n);
    scan_tops<<<1, SCAN_BLK, 0, s2>>>(nb, n);
    add_offsets<<<(n + 255) / 256, 256, 0, s2>>>(n);
    scatter_kernel<<<(e + 255) / 256, 256, 0, s2>>>(ei, e);
    cudaEventRecord(ev1, s2);

    // operand split, then pipelined GEMM, on main stream
    const int tot4 = n * (FDIM / 4) + 512 * (FDIM / 4);
    split_all<<<(tot4 + 255) / 256, 256>>>(x, Wq, Wk, Wv, Ws, n);
    dim3 gg((n + 127) / 128, 4);
    gemm_mma<<<gg, 256>>>(bq, bk, bv, bs, n);

    cudaStreamWaitEvent(0, ev1, 0);
    edge_attn<<<(n + EA_WARPS - 1) / EA_WARPS, 256>>>(out, n);
}

// round 13
// speedup vs baseline: 1.4788x; 1.2205x over previous
#include <cuda_runtime.h>
#include <cuda_bf16.h>
#include <cuda_fp16.h>
#include <math.h>
#include <stdint.h>

// Problem constants
#define NMAX 50000
#define EMAX 800000
#define FDIM 128
#define SCAN_BLK 512
#define MPAD 128   // row padding so cp.async can safely over-read the last tile

// ---------------- device scratch ----------------
__device__ float  g_q[NMAX * FDIM];
__device__ float  g_skip[NMAX * FDIM];
// Interleaved kv: per node 256 halves; lane-l group at l*8: [k(4l..4l+3) | v(4l..4l+3)]
__device__ __half g_kv[NMAX * 256];
// fp16 operands
__device__ __half g_xh[(NMAX + MPAD) * FDIM];
__device__ __half g_wh[512 * FDIM];
__device__ int    g_count[NMAX];
__device__ int    g_rowptr[NMAX + 1];
__device__ int    g_fill[NMAX];
__device__ int    g_esrc[EMAX];
__device__ int    g_bsum[1024];
__device__ int    g_boff[1024];

// ---------------- helpers ----------------
__device__ __forceinline__ uint32_t smem_u32(const void* p) {
    uint32_t a;
    asm("{ .reg .u64 t; cvta.to.shared.u64 t, %1; cvt.u32.u64 %0, t; }" : "=r"(a) : "l"(p));
    return a;
}
__device__ __forceinline__ void cp16(uint32_t dst, const void* src) {
    asm volatile("cp.async.cg.shared.global [%0], [%1], 16;" :: "r"(dst), "l"(src));
}

// ---------------- 0) convert x and W to fp16 ----------------
__global__ void split_all(const float* __restrict__ x,
                          const float* __restrict__ Wq, const float* __restrict__ Wk,
                          const float* __restrict__ Wv, const float* __restrict__ Ws,
                          int n)
{
    const int nx = n * (FDIM / 4);
    const int i = blockIdx.x * blockDim.x + threadIdx.x;
    if (i < nx) {
        float4 v = *(const float4*)(x + (size_t)i * 4);
        ushort4 h4;
        h4.x = __half_as_ushort(__float2half_rn(v.x));
        h4.y = __half_as_ushort(__float2half_rn(v.y));
        h4.z = __half_as_ushort(__float2half_rn(v.z));
        h4.w = __half_as_ushort(__float2half_rn(v.w));
        *(ushort4*)(g_xh + (size_t)i * 4) = h4;
    } else {
        const int j = i - nx;                 // over 512*32 float4s
        if (j >= 512 * (FDIM / 4)) return;
        const int m = j >> 12;
        const int r = j & 4095;
        const float* W = (m == 0) ? Wq : (m == 1) ? Wk : (m == 2) ? Wv : Ws;
        float4 v = *(const float4*)(W + (size_t)r * 4);
        ushort4 h4;
        h4.x = __half_as_ushort(__float2half_rn(v.x));
        h4.y = __half_as_ushort(__float2half_rn(v.y));
        h4.z = __half_as_ushort(__float2half_rn(v.z));
        h4.w = __half_as_ushort(__float2half_rn(v.w));
        *(ushort4*)(g_wh + (size_t)j * 4) = h4;
    }
}

// ---------------- 1) cp.async-pipelined fp16 mma GEMM (single pass, BK=32) ----------------
#define APAD32 40   // 80B row stride -> conflict-free frag loads
#define NT4 4       // 128 / 32

__device__ __forceinline__ void mma_fp16(float c[4], const uint32_t a[4], const uint32_t b[2]) {
    asm volatile(
        "mma.sync.aligned.m16n8k16.row.col.f32.f16.f16.f32 "
        "{%0,%1,%2,%3}, {%4,%5,%6,%7}, {%8,%9}, {%0,%1,%2,%3};"
        : "+f"(c[0]), "+f"(c[1]), "+f"(c[2]), "+f"(c[3])
        : "r"(a[0]), "r"(a[1]), "r"(a[2]), "r"(a[3]), "r"(b[0]), "r"(b[1]));
}

__global__ __launch_bounds__(256) void gemm_mma(
    const float* __restrict__ bq, const float* __restrict__ bk,
    const float* __restrict__ bv, const float* __restrict__ bs,
    int M)
{
    // [stage][array: A,B][128 rows * APAD32] = 40 KB
    __shared__ __half sm[2][2][128 * APAD32];

    const float* bias;
    switch (blockIdx.y) {
        case 0:  bias = bq; break;
        case 1:  bias = bk; break;
        case 2:  bias = bv; break;
        default: bias = bs; break;
    }
    const bool to_half = (blockIdx.y == 1) || (blockIdx.y == 2);
    float* outf = (blockIdx.y == 0) ? g_q : g_skip;
    const int hsub = (blockIdx.y == 1) ? 0 : 4;

    const int tid  = threadIdx.x;
    const int wid  = tid >> 5;
    const int lane = tid & 31;
    const int wm   = wid >> 2;
    const int wn   = wid & 3;
    const int m0   = blockIdx.x * 128;
    const int nb0  = blockIdx.y * 128;     // W row block
    const int qrow = lane >> 2;
    const int qk   = (lane & 3) * 2;

    // cp.async coords: per array per tile 512 chunks of 16B; 2 per thread
    const int f0 = tid, f1 = tid + 256;
    const int r0c = f0 >> 2, c0c = (f0 & 3) * 8;     // row, halves offset
    const int r1c = f1 >> 2, c1c = (f1 & 3) * 8;
    const uint32_t so0 = (uint32_t)(r0c * APAD32 + c0c) * 2;
    const uint32_t so1 = (uint32_t)(r1c * APAD32 + c1c) * 2;
    const size_t gaA0 = (size_t)(m0 + r0c) * FDIM + c0c;
    const size_t gaA1 = (size_t)(m0 + r1c) * FDIM + c1c;
    const size_t gaB0 = (size_t)(nb0 + r0c) * FDIM + c0c;
    const size_t gaB1 = (size_t)(nb0 + r1c) * FDIM + c1c;
    const uint32_t sb = smem_u32(&sm[0][0][0]);
    const uint32_t SA = 128 * APAD32 * 2;          // bytes per array
    const uint32_t SS = 2 * SA;                    // bytes per stage

    float c[4][4][4];
    #pragma unroll
    for (int mi = 0; mi < 4; mi++)
        #pragma unroll
        for (int nj = 0; nj < 4; nj++)
            #pragma unroll
            for (int r = 0; r < 4; r++) c[mi][nj][r] = 0.f;

    // prologue: tile 0 -> stage 0
    {
        cp16(sb + 0 * SA + so0, g_xh + gaA0);
        cp16(sb + 0 * SA + so1, g_xh + gaA1);
        cp16(sb + 1 * SA + so0, g_wh + gaB0);
        cp16(sb + 1 * SA + so1, g_wh + gaB1);
        asm volatile("cp.async.commit_group;");
    }

    for (int ct = 0; ct < NT4; ct++) {
        const int s = ct & 1;
        if (ct + 1 < NT4) {
            const int kt = (ct + 1) * 32;
            const uint32_t st = sb + ((ct + 1) & 1) * SS;
            cp16(st + 0 * SA + so0, g_xh + gaA0 + kt);
            cp16(st + 0 * SA + so1, g_xh + gaA1 + kt);
            cp16(st + 1 * SA + so0, g_wh + gaB0 + kt);
            cp16(st + 1 * SA + so1, g_wh + gaB1 + kt);
            asm volatile("cp.async.commit_group;");
            asm volatile("cp.async.wait_group 1;");
        } else {
            asm volatile("cp.async.wait_group 0;");
        }
        __syncthreads();

        const __half* Ab = sm[s][0];
        const __half* Bb = sm[s][1];
        #pragma unroll
        for (int ks = 0; ks < 2; ks++) {
            const int kb = ks * 16 + qk;
            uint32_t a[4][4], b[4][2];
            #pragma unroll
            for (int mi = 0; mi < 4; mi++) {
                const int row = wm * 64 + mi * 16 + qrow;
                a[mi][0] = *(const uint32_t*)(Ab + row * APAD32 + kb);
                a[mi][1] = *(const uint32_t*)(Ab + (row + 8) * APAD32 + kb);
                a[mi][2] = *(const uint32_t*)(Ab + row * APAD32 + kb + 8);
                a[mi][3] = *(const uint32_t*)(Ab + (row + 8) * APAD32 + kb + 8);
            }
            #pragma unroll
            for (int nj = 0; nj < 4; nj++) {
                const int col = wn * 32 + nj * 8 + qrow;
                b[nj][0] = *(const uint32_t*)(Bb + col * APAD32 + kb);
                b[nj][1] = *(const uint32_t*)(Bb + col * APAD32 + kb + 8);
            }
            #pragma unroll
            for (int mi = 0; mi < 4; mi++)
                #pragma unroll
                for (int nj = 0; nj < 4; nj++)
                    mma_fp16(c[mi][nj], a[mi], b[nj]);
        }
        __syncthreads();
    }

    float2 bj[4];
    #pragma unroll
    for (int nj = 0; nj < 4; nj++) {
        const int col = wn * 32 + nj * 8 + (lane & 3) * 2;
        bj[nj] = *(const float2*)(bias + col);
    }
    #pragma unroll
    for (int mi = 0; mi < 4; mi++) {
        const int r0 = m0 + wm * 64 + mi * 16 + qrow;
        #pragma unroll
        for (int nj = 0; nj < 4; nj++) {
            const int col = wn * 32 + nj * 8 + (lane & 3) * 2;
            const float v00 = c[mi][nj][0] + bj[nj].x;
            const float v01 = c[mi][nj][1] + bj[nj].y;
            const float v10 = c[mi][nj][2] + bj[nj].x;
            const float v11 = c[mi][nj][3] + bj[nj].y;
            if (to_half) {
                const int off = ((col >> 2) << 3) + (col & 3) + hsub;
                if (r0 < M)
                    *(__half2*)(g_kv + (size_t)r0 * 256 + off) = __floats2half2_rn(v00, v01);
                if (r0 + 8 < M)
                    *(__half2*)(g_kv + (size_t)(r0 + 8) * 256 + off) = __floats2half2_rn(v10, v11);
            } else {
                if (r0 < M)
                    *(float2*)(outf + (size_t)r0 * 128 + col) = make_float2(v00, v01);
                if (r0 + 8 < M)
                    *(float2*)(outf + (size_t)(r0 + 8) * 128 + col) = make_float2(v10, v11);
            }
        }
    }
}

// ---------------- 2) CSR build ----------------
__global__ void zero_counts(int n)
{
    int i = blockIdx.x * blockDim.x + threadIdx.x;
    if (i < n) g_count[i] = 0;
}

__global__ void hist_kernel(const int* __restrict__ ei, int e)
{
    int i = blockIdx.x * blockDim.x + threadIdx.x;
    if (i < e) atomicAdd(&g_count[ei[e + i]], 1);
}

__global__ void scan_blocks(int n)
{
    __shared__ int sh[SCAN_BLK];
    const int t = threadIdx.x;
    const int i = blockIdx.x * SCAN_BLK + t;
    const int v = (i < n) ? g_count[i] : 0;
    sh[t] = v;
    __syncthreads();
    #pragma unroll
    for (int off = 1; off < SCAN_BLK; off <<= 1) {
        int u = (t >= off) ? sh[t - off] : 0;
        __syncthreads();
        sh[t] += u;
        __syncthreads();
    }
    if (i < n) g_rowptr[i] = sh[t] - v;
    if (t == SCAN_BLK - 1) g_bsum[blockIdx.x] = sh[t];
}

__global__ void scan_tops(int nb, int n)
{
    __shared__ int sh[SCAN_BLK];
    const int t = threadIdx.x;
    const int v = (t < nb) ? g_bsum[t] : 0;
    sh[t] = v;
    __syncthreads();
    #pragma unroll
    for (int off = 1; off < SCAN_BLK; off <<= 1) {
        int u = (t >= off) ? sh[t - off] : 0;
        __syncthreads();
        sh[t] += u;
        __syncthreads();
    }
    g_boff[t] = sh[t] - v;
    if (t == SCAN_BLK - 1) g_rowptr[n] = sh[t];
}

__global__ void add_offsets(int n)
{
    const int i = blockIdx.x * blockDim.x + threadIdx.x;
    if (i < n) {
        const int r = g_rowptr[i] + g_boff[i / SCAN_BLK];
        g_rowptr[i] = r;
        g_fill[i]   = r;
    }
}

__global__ void scatter_kernel(const int* __restrict__ ei, int e)
{
    int i = blockIdx.x * blockDim.x + threadIdx.x;
    if (i < e) {
        int dst  = ei[e + i];
        int slot = atomicAdd(&g_fill[dst], 1);
        g_esrc[slot] = ei[i];
    }
}

// ---------------- 3) fused attention aggregation: cp.async gather pipeline ----------------
#define EA_WARPS 8
__global__ __launch_bounds__(256) void edge_attn(float* __restrict__ out, int n)
{
    __shared__ char kvbuf[EA_WARPS][2][2048];   // 32 KB: 2 stages x 4 edges x 512B per warp

    const int wInB = threadIdx.x >> 5;
    const int lane = threadIdx.x & 31;
    const int node = blockIdx.x * EA_WARPS + wInB;
    if (node >= n) return;

    const float scale = 0.17677669529663687f;  // 1/sqrt(32)
    float4 q4 = *(const float4*)(g_q + (size_t)node * 128 + lane * 4);
    q4.x *= scale; q4.y *= scale; q4.z *= scale; q4.w *= scale;

    float4 acc = make_float4(0.f, 0.f, 0.f, 0.f);
    float den = 0.f;

    const int beg = g_rowptr[node];
    const int end = g_rowptr[node + 1];
    const int ngrp = (end - beg) >> 2;
    const uint32_t sbase = smem_u32(&kvbuf[wInB][0][0]);

    int sB[4];
    if (ngrp > 0) {
        int sA[4];
        #pragma unroll
        for (int u = 0; u < 4; u++) sA[u] = __ldg(&g_esrc[beg + u]);
        #pragma unroll
        for (int u = 0; u < 4; u++)
            cp16(sbase + u * 512 + lane * 16, g_kv + (size_t)sA[u] * 256 + lane * 8);
        asm volatile("cp.async.commit_group;");
        if (ngrp > 1) {
            #pragma unroll
            for (int u = 0; u < 4; u++) sB[u] = __ldg(&g_esrc[beg + 4 + u]);
        }
    }

    for (int g = 0; g < ngrp; g++) {
        if (g + 1 < ngrp) {
            const uint32_t st = sbase + ((g + 1) & 1) * 2048;
            #pragma unroll
            for (int u = 0; u < 4; u++)
                cp16(st + u * 512 + lane * 16, g_kv + (size_t)sB[u] * 256 + lane * 8);
            asm volatile("cp.async.commit_group;");
            if (g + 2 < ngrp) {
                #pragma unroll
                for (int u = 0; u < 4; u++) sB[u] = __ldg(&g_esrc[beg + (g + 2) * 4 + u]);
            }
            asm volatile("cp.async.wait_group 1;");
        } else {
            asm volatile("cp.async.wait_group 0;");
        }

        const uint32_t cur = sbase + (g & 1) * 2048;
        uint4 kv[4];
        #pragma unroll
        for (int u = 0; u < 4; u++) {
            asm("ld.shared.v4.u32 {%0,%1,%2,%3}, [%4];"
                : "=r"(kv[u].x), "=r"(kv[u].y), "=r"(kv[u].z), "=r"(kv[u].w)
                : "r"(cur + u * 512 + lane * 16));
        }
        float p[4];
        #pragma unroll
        for (int u = 0; u < 4; u++) {
            const float2 ka = __half22float2(*(const __half2*)&kv[u].x);
            const float2 kb = __half22float2(*(const __half2*)&kv[u].y);
            p[u] = q4.x * ka.x + q4.y * ka.y + q4.z * kb.x + q4.w * kb.y;
        }
        #pragma unroll
        for (int u = 0; u < 4; u++) p[u] += __shfl_xor_sync(0xffffffffu, p[u], 1, 8);
        #pragma unroll
        for (int u = 0; u < 4; u++) p[u] += __shfl_xor_sync(0xffffffffu, p[u], 2, 8);
        #pragma unroll
        for (int u = 0; u < 4; u++) p[u] += __shfl_xor_sync(0xffffffffu, p[u], 4, 8);
        #pragma unroll
        for (int u = 0; u < 4; u++) {
            const float w = __expf(p[u]);
            const float2 va = __half22float2(*(const __half2*)&kv[u].z);
            const float2 vb = __half22float2(*(const __half2*)&kv[u].w);
            den += w;
            acc.x = fmaf(w, va.x, acc.x);
            acc.y = fmaf(w, va.y, acc.y);
            acc.z = fmaf(w, vb.x, acc.z);
            acc.w = fmaf(w, vb.y, acc.w);
        }
    }

    // tail (deg % 4) via direct loads
    for (int i = beg + ngrp * 4; i < end; i++) {
        const int s0 = __ldg(&g_esrc[i]);
        const uint4 kv0 = *(const uint4*)(g_kv + (size_t)s0 * 256 + lane * 8);
        const float2 ka = __half22float2(*(const __half2*)&kv0.x);
        const float2 kb = __half22float2(*(const __half2*)&kv0.y);
        float p0 = q4.x * ka.x + q4.y * ka.y + q4.z * kb.x + q4.w * kb.y;
        p0 += __shfl_xor_sync(0xffffffffu, p0, 1, 8);
        p0 += __shfl_xor_sync(0xffffffffu, p0, 2, 8);
        p0 += __shfl_xor_sync(0xffffffffu, p0, 4, 8);
        const float w = __expf(p0);
        const float2 va = __half22float2(*(const __half2*)&kv0.z);
        const float2 vb = __half22float2(*(const __half2*)&kv0.w);
        den += w;
        acc.x = fmaf(w, va.x, acc.x);
        acc.y = fmaf(w, va.y, acc.y);
        acc.z = fmaf(w, vb.x, acc.z);
        acc.w = fmaf(w, vb.y, acc.w);
    }

    const float inv = (den > 0.f) ? (1.0f / den) : 0.f;
    const float4 sk = *(const float4*)(g_skip + (size_t)node * 128 + lane * 4);
    float4 o;
    o.x = fmaxf(fmaf(acc.x, inv, sk.x), 0.f);
    o.y = fmaxf(fmaf(acc.y, inv, sk.y), 0.f);
    o.z = fmaxf(fmaf(acc.z, inv, sk.z), 0.f);
    o.w = fmaxf(fmaf(acc.w, inv, sk.w), 0.f);
    *(float4*)(out + (size_t)node * 128 + lane * 4) = o;
}

// ---------------- host launcher ----------------
extern "C" void kernel_launch(void* const* d_in, const int* in_sizes, int n_in,
                              void* d_out, int out_size)
{
    const float* x  = (const float*)d_in[0];
    const int*   ei = (const int*)  d_in[1];
    const float* Wq = (const float*)d_in[2];
    const float* bq = (const float*)d_in[3];
    const float* Wk = (const float*)d_in[4];
    const float* bk = (const float*)d_in[5];
    const float* Wv = (const float*)d_in[6];
    const float* bv = (const float*)d_in[7];
    const float* Ws = (const float*)d_in[8];
    const float* bs = (const float*)d_in[9];
    float* out = (float*)d_out;

    const int n = in_sizes[0] / FDIM;   // 50000
    const int e = in_sizes[1] / 2;      // 800000
    const int nb = (n + SCAN_BLK - 1) / SCAN_BLK;

    // Side stream: CSR build overlaps convert + GEMM.
    cudaStream_t s2;
    cudaEvent_t ev0, ev1;
    cudaStreamCreateWithFlags(&s2, cudaStreamNonBlocking);
    cudaEventCreateWithFlags(&ev0, cudaEventDisableTiming);
    cudaEventCreateWithFlags(&ev1, cudaEventDisableTiming);

    cudaEventRecord(ev0, 0);
    cudaStreamWaitEvent(s2, ev0, 0);

    zero_counts<<<(n + 255) / 256, 256, 0, s2>>>(n);
    hist_kernel<<<(e + 255) / 256, 256, 0, s2>>>(ei, e);
    scan_blocks<<<nb, SCAN_BLK, 0, s2>>>(n);
    scan_tops<<<1, SCAN_BLK, 0, s2>>>(nb, n);
    add_offsets<<<(n + 255) / 256, 256, 0, s2>>>(n);
    scatter_kernel<<<(e + 255) / 256, 256, 0, s2>>>(ei, e);
    cudaEventRecord(ev1, s2);

    // fp16 convert, then pipelined GEMM, on main stream
    const int tot4 = n * (FDIM / 4) + 512 * (FDIM / 4);
    split_all<<<(tot4 + 255) / 256, 256>>>(x, Wq, Wk, Wv, Ws, n);
    dim3 gg((n + 127) / 128, 4);
    gemm_mma<<<gg, 256>>>(bq, bk, bv, bs, n);

    cudaStreamWaitEvent(0, ev1, 0);
    edge_attn<<<(n + EA_WARPS - 1) / EA_WARPS, 256>>>(out, n);
}

// round 14
// speedup vs baseline: 1.5183x; 1.0268x over previous
#include <cuda_runtime.h>
#include <cuda_bf16.h>
#include <cuda_fp16.h>
#include <math.h>
#include <stdint.h>

// Problem constants
#define NMAX 50000
#define EMAX 800000
#define FDIM 128
#define SCAN_BLK 512
#define MPAD 128   // row padding so cp.async can safely over-read the last tile

// ---------------- device scratch ----------------
__device__ __half g_qh[NMAX * FDIM];     // q * (1/sqrt(C)), fp16
__device__ __half g_skh[NMAX * FDIM];    // skip projection, fp16
// Interleaved kv: per node 256 halves; lane-l group at l*8: [k(4l..4l+3) | v(4l..4l+3)]
__device__ __half g_kv[NMAX * 256];
// fp16 operands
__device__ __half g_xh[(NMAX + MPAD) * FDIM];
__device__ __half g_wh[512 * FDIM];
__device__ int    g_count[NMAX];
__device__ int    g_rowptr[NMAX + 1];
__device__ int    g_fill[NMAX];
__device__ int    g_esrc[EMAX];
__device__ int    g_bsum[1024];
__device__ int    g_boff[1024];

// ---------------- helpers ----------------
__device__ __forceinline__ uint32_t smem_u32(const void* p) {
    uint32_t a;
    asm("{ .reg .u64 t; cvta.to.shared.u64 t, %1; cvt.u32.u64 %0, t; }" : "=r"(a) : "l"(p));
    return a;
}
__device__ __forceinline__ void cp16(uint32_t dst, const void* src) {
    asm volatile("cp.async.cg.shared.global [%0], [%1], 16;" :: "r"(dst), "l"(src));
}

// ---------------- 0) convert x and W to fp16 ----------------
__global__ void split_all(const float* __restrict__ x,
                          const float* __restrict__ Wq, const float* __restrict__ Wk,
                          const float* __restrict__ Wv, const float* __restrict__ Ws,
                          int n)
{
    const int nx = n * (FDIM / 4);
    const int i = blockIdx.x * blockDim.x + threadIdx.x;
    if (i < nx) {
        float4 v = *(const float4*)(x + (size_t)i * 4);
        ushort4 h4;
        h4.x = __half_as_ushort(__float2half_rn(v.x));
        h4.y = __half_as_ushort(__float2half_rn(v.y));
        h4.z = __half_as_ushort(__float2half_rn(v.z));
        h4.w = __half_as_ushort(__float2half_rn(v.w));
        *(ushort4*)(g_xh + (size_t)i * 4) = h4;
    } else {
        const int j = i - nx;                 // over 512*32 float4s
        if (j >= 512 * (FDIM / 4)) return;
        const int m = j >> 12;
        const int r = j & 4095;
        const float* W = (m == 0) ? Wq : (m == 1) ? Wk : (m == 2) ? Wv : Ws;
        float4 v = *(const float4*)(W + (size_t)r * 4);
        ushort4 h4;
        h4.x = __half_as_ushort(__float2half_rn(v.x));
        h4.y = __half_as_ushort(__float2half_rn(v.y));
        h4.z = __half_as_ushort(__float2half_rn(v.z));
        h4.w = __half_as_ushort(__float2half_rn(v.w));
        *(ushort4*)(g_wh + (size_t)j * 4) = h4;
    }
}

// ---------------- 1) cp.async-pipelined fp16 mma GEMM (single pass, BK=32) ----------------
#define APAD32 40   // 80B row stride -> conflict-free frag loads
#define NT4 4       // 128 / 32

__device__ __forceinline__ void mma_fp16(float c[4], const uint32_t a[4], const uint32_t b[2]) {
    asm volatile(
        "mma.sync.aligned.m16n8k16.row.col.f32.f16.f16.f32 "
        "{%0,%1,%2,%3}, {%4,%5,%6,%7}, {%8,%9}, {%0,%1,%2,%3};"
        : "+f"(c[0]), "+f"(c[1]), "+f"(c[2]), "+f"(c[3])
        : "r"(a[0]), "r"(a[1]), "r"(a[2]), "r"(a[3]), "r"(b[0]), "r"(b[1]));
}

__global__ __launch_bounds__(256) void gemm_mma(
    const float* __restrict__ bq, const float* __restrict__ bk,
    const float* __restrict__ bv, const float* __restrict__ bs,
    int M)
{
    // [stage][array: A,B][128 rows * APAD32] = 40 KB
    __shared__ __half sm[2][2][128 * APAD32];

    const float* bias;
    switch (blockIdx.y) {
        case 0:  bias = bq; break;
        case 1:  bias = bk; break;
        case 2:  bias = bv; break;
        default: bias = bs; break;
    }
    // All four outputs now fp16:
    //  y==0 -> g_qh (scaled by 1/sqrt(C)); y==3 -> g_skh; y==1/2 -> g_kv interleaved
    const bool to_kv = (blockIdx.y == 1) || (blockIdx.y == 2);
    __half* outh = (blockIdx.y == 0) ? g_qh : g_skh;
    const int hsub = (blockIdx.y == 1) ? 0 : 4;
    const float oscale = (blockIdx.y == 0) ? 0.17677669529663687f : 1.0f;

    const int tid  = threadIdx.x;
    const int wid  = tid >> 5;
    const int lane = tid & 31;
    const int wm   = wid >> 2;
    const int wn   = wid & 3;
    const int m0   = blockIdx.x * 128;
    const int nb0  = blockIdx.y * 128;     // W row block
    const int qrow = lane >> 2;
    const int qk   = (lane & 3) * 2;

    // cp.async coords: per array per tile 512 chunks of 16B; 2 per thread
    const int f0 = tid, f1 = tid + 256;
    const int r0c = f0 >> 2, c0c = (f0 & 3) * 8;     // row, halves offset
    const int r1c = f1 >> 2, c1c = (f1 & 3) * 8;
    const uint32_t so0 = (uint32_t)(r0c * APAD32 + c0c) * 2;
    const uint32_t so1 = (uint32_t)(r1c * APAD32 + c1c) * 2;
    const size_t gaA0 = (size_t)(m0 + r0c) * FDIM + c0c;
    const size_t gaA1 = (size_t)(m0 + r1c) * FDIM + c1c;
    const size_t gaB0 = (size_t)(nb0 + r0c) * FDIM + c0c;
    const size_t gaB1 = (size_t)(nb0 + r1c) * FDIM + c1c;
    const uint32_t sb = smem_u32(&sm[0][0][0]);
    const uint32_t SA = 128 * APAD32 * 2;          // bytes per array
    const uint32_t SS = 2 * SA;                    // bytes per stage

    float c[4][4][4];
    #pragma unroll
    for (int mi = 0; mi < 4; mi++)
        #pragma unroll
        for (int nj = 0; nj < 4; nj++)
            #pragma unroll
            for (int r = 0; r < 4; r++) c[mi][nj][r] = 0.f;

    // prologue: tile 0 -> stage 0
    {
        cp16(sb + 0 * SA + so0, g_xh + gaA0);
        cp16(sb + 0 * SA + so1, g_xh + gaA1);
        cp16(sb + 1 * SA + so0, g_wh + gaB0);
        cp16(sb + 1 * SA + so1, g_wh + gaB1);
        asm volatile("cp.async.commit_group;");
    }

    for (int ct = 0; ct < NT4; ct++) {
        const int s = ct & 1;
        if (ct + 1 < NT4) {
            const int kt = (ct + 1) * 32;
            const uint32_t st = sb + ((ct + 1) & 1) * SS;
            cp16(st + 0 * SA + so0, g_xh + gaA0 + kt);
            cp16(st + 0 * SA + so1, g_xh + gaA1 + kt);
            cp16(st + 1 * SA + so0, g_wh + gaB0 + kt);
            cp16(st + 1 * SA + so1, g_wh + gaB1 + kt);
            asm volatile("cp.async.commit_group;");
            asm volatile("cp.async.wait_group 1;");
        } else {
            asm volatile("cp.async.wait_group 0;");
        }
        __syncthreads();

        const __half* Ab = sm[s][0];
        const __half* Bb = sm[s][1];
        #pragma unroll
        for (int ks = 0; ks < 2; ks++) {
            const int kb = ks * 16 + qk;
            uint32_t a[4][4], b[4][2];
            #pragma unroll
            for (int mi = 0; mi < 4; mi++) {
                const int row = wm * 64 + mi * 16 + qrow;
                a[mi][0] = *(const uint32_t*)(Ab + row * APAD32 + kb);
                a[mi][1] = *(const uint32_t*)(Ab + (row + 8) * APAD32 + kb);
                a[mi][2] = *(const uint32_t*)(Ab + row * APAD32 + kb + 8);
                a[mi][3] = *(const uint32_t*)(Ab + (row + 8) * APAD32 + kb + 8);
            }
            #pragma unroll
            for (int nj = 0; nj < 4; nj++) {
                const int col = wn * 32 + nj * 8 + qrow;
                b[nj][0] = *(const uint32_t*)(Bb + col * APAD32 + kb);
                b[nj][1] = *(const uint32_t*)(Bb + col * APAD32 + kb + 8);
            }
            #pragma unroll
            for (int mi = 0; mi < 4; mi++)
                #pragma unroll
                for (int nj = 0; nj < 4; nj++)
                    mma_fp16(c[mi][nj], a[mi], b[nj]);
        }
        __syncthreads();
    }

    float2 bj[4];
    #pragma unroll
    for (int nj = 0; nj < 4; nj++) {
        const int col = wn * 32 + nj * 8 + (lane & 3) * 2;
        bj[nj] = *(const float2*)(bias + col);
    }
    #pragma unroll
    for (int mi = 0; mi < 4; mi++) {
        const int r0 = m0 + wm * 64 + mi * 16 + qrow;
        #pragma unroll
        for (int nj = 0; nj < 4; nj++) {
            const int col = wn * 32 + nj * 8 + (lane & 3) * 2;
            const float v00 = (c[mi][nj][0] + bj[nj].x) * oscale;
            const float v01 = (c[mi][nj][1] + bj[nj].y) * oscale;
            const float v10 = (c[mi][nj][2] + bj[nj].x) * oscale;
            const float v11 = (c[mi][nj][3] + bj[nj].y) * oscale;
            if (to_kv) {
                const int off = ((col >> 2) << 3) + (col & 3) + hsub;
                if (r0 < M)
                    *(__half2*)(g_kv + (size_t)r0 * 256 + off) = __floats2half2_rn(v00, v01);
                if (r0 + 8 < M)
                    *(__half2*)(g_kv + (size_t)(r0 + 8) * 256 + off) = __floats2half2_rn(v10, v11);
            } else {
                if (r0 < M)
                    *(__half2*)(outh + (size_t)r0 * 128 + col) = __floats2half2_rn(v00, v01);
                if (r0 + 8 < M)
                    *(__half2*)(outh + (size_t)(r0 + 8) * 128 + col) = __floats2half2_rn(v10, v11);
            }
        }
    }
}

// ---------------- 2) CSR build ----------------
__global__ void zero_counts(int n)
{
    int i = blockIdx.x * blockDim.x + threadIdx.x;
    if (i < n) g_count[i] = 0;
}

__global__ void hist_kernel(const int* __restrict__ ei, int e)
{
    int i = blockIdx.x * blockDim.x + threadIdx.x;
    if (i < e) atomicAdd(&g_count[ei[e + i]], 1);
}

__global__ void scan_blocks(int n)
{
    __shared__ int sh[SCAN_BLK];
    const int t = threadIdx.x;
    const int i = blockIdx.x * SCAN_BLK + t;
    const int v = (i < n) ? g_count[i] : 0;
    sh[t] = v;
    __syncthreads();
    #pragma unroll
    for (int off = 1; off < SCAN_BLK; off <<= 1) {
        int u = (t >= off) ? sh[t - off] : 0;
        __syncthreads();
        sh[t] += u;
        __syncthreads();
    }
    if (i < n) g_rowptr[i] = sh[t] - v;
    if (t == SCAN_BLK - 1) g_bsum[blockIdx.x] = sh[t];
}

__global__ void scan_tops(int nb, int n)
{
    __shared__ int sh[SCAN_BLK];
    const int t = threadIdx.x;
    const int v = (t < nb) ? g_bsum[t] : 0;
    sh[t] = v;
    __syncthreads();
    #pragma unroll
    for (int off = 1; off < SCAN_BLK; off <<= 1) {
        int u = (t >= off) ? sh[t - off] : 0;
        __syncthreads();
        sh[t] += u;
        __syncthreads();
    }
    g_boff[t] = sh[t] - v;
    if (t == SCAN_BLK - 1) g_rowptr[n] = sh[t];
}

__global__ void add_offsets(int n)
{
    const int i = blockIdx.x * blockDim.x + threadIdx.x;
    if (i < n) {
        const int r = g_rowptr[i] + g_boff[i / SCAN_BLK];
        g_rowptr[i] = r;
        g_fill[i]   = r;
    }
}

__global__ void scatter_kernel(const int* __restrict__ ei, int e)
{
    int i = blockIdx.x * blockDim.x + threadIdx.x;
    if (i < e) {
        int dst  = ei[e + i];
        int slot = atomicAdd(&g_fill[dst], 1);
        g_esrc[slot] = ei[i];
    }
}

// ---------------- 3) fused attention aggregation: cp.async gather pipeline ----------------
#define EA_WARPS 8
__global__ __launch_bounds__(256) void edge_attn(float* __restrict__ out, int n)
{
    __shared__ char kvbuf[EA_WARPS][2][2048];   // 32 KB: 2 stages x 4 edges x 512B per warp

    const int wInB = threadIdx.x >> 5;
    const int lane = threadIdx.x & 31;
    const int node = blockIdx.x * EA_WARPS + wInB;
    if (node >= n) return;

    // q already scaled by 1/sqrt(C) in the GEMM epilogue
    float4 q4;
    {
        const uint2 qu = *(const uint2*)(g_qh + (size_t)node * 128 + lane * 4);
        const float2 qa = __half22float2(*(const __half2*)&qu.x);
        const float2 qb = __half22float2(*(const __half2*)&qu.y);
        q4 = make_float4(qa.x, qa.y, qb.x, qb.y);
    }

    float4 acc = make_float4(0.f, 0.f, 0.f, 0.f);
    float den = 0.f;

    const int beg = g_rowptr[node];
    const int end = g_rowptr[node + 1];
    const int ngrp = (end - beg) >> 2;
    const uint32_t sbase = smem_u32(&kvbuf[wInB][0][0]);

    int sB[4];
    if (ngrp > 0) {
        int sA[4];
        #pragma unroll
        for (int u = 0; u < 4; u++) sA[u] = __ldg(&g_esrc[beg + u]);
        #pragma unroll
        for (int u = 0; u < 4; u++)
            cp16(sbase + u * 512 + lane * 16, g_kv + (size_t)sA[u] * 256 + lane * 8);
        asm volatile("cp.async.commit_group;");
        if (ngrp > 1) {
            #pragma unroll
            for (int u = 0; u < 4; u++) sB[u] = __ldg(&g_esrc[beg + 4 + u]);
        }
    }

    for (int g = 0; g < ngrp; g++) {
        if (g + 1 < ngrp) {
            const uint32_t st = sbase + ((g + 1) & 1) * 2048;
            #pragma unroll
            for (int u = 0; u < 4; u++)
                cp16(st + u * 512 + lane * 16, g_kv + (size_t)sB[u] * 256 + lane * 8);
            asm volatile("cp.async.commit_group;");
            if (g + 2 < ngrp) {
                #pragma unroll
                for (int u = 0; u < 4; u++) sB[u] = __ldg(&g_esrc[beg + (g + 2) * 4 + u]);
            }
            asm volatile("cp.async.wait_group 1;");
        } else {
            asm volatile("cp.async.wait_group 0;");
        }

        const uint32_t cur = sbase + (g & 1) * 2048;
        uint4 kv[4];
        #pragma unroll
        for (int u = 0; u < 4; u++) {
            asm("ld.shared.v4.u32 {%0,%1,%2,%3}, [%4];"
                : "=r"(kv[u].x), "=r"(kv[u].y), "=r"(kv[u].z), "=r"(kv[u].w)
                : "r"(cur + u * 512 + lane * 16));
        }
        float p[4];
        #pragma unroll
        for (int u = 0; u < 4; u++) {
            const float2 ka = __half22float2(*(const __half2*)&kv[u].x);
            const float2 kb = __half22float2(*(const __half2*)&kv[u].y);
            p[u] = q4.x * ka.x + q4.y * ka.y + q4.z * kb.x + q4.w * kb.y;
        }
        #pragma unroll
        for (int u = 0; u < 4; u++) p[u] += __shfl_xor_sync(0xffffffffu, p[u], 1, 8);
        #pragma unroll
        for (int u = 0; u < 4; u++) p[u] += __shfl_xor_sync(0xffffffffu, p[u], 2, 8);
        #pragma unroll
        for (int u = 0; u < 4; u++) p[u] += __shfl_xor_sync(0xffffffffu, p[u], 4, 8);
        #pragma unroll
        for (int u = 0; u < 4; u++) {
            const float w = __expf(p[u]);
            const float2 va = __half22float2(*(const __half2*)&kv[u].z);
            const float2 vb = __half22float2(*(const __half2*)&kv[u].w);
            den += w;
            acc.x = fmaf(w, va.x, acc.x);
            acc.y = fmaf(w, va.y, acc.y);
            acc.z = fmaf(w, vb.x, acc.z);
            acc.w = fmaf(w, vb.y, acc.w);
        }
    }

    // tail (deg % 4) via direct loads
    for (int i = beg + ngrp * 4; i < end; i++) {
        const int s0 = __ldg(&g_esrc[i]);
        const uint4 kv0 = *(const uint4*)(g_kv + (size_t)s0 * 256 + lane * 8);
        const float2 ka = __half22float2(*(const __half2*)&kv0.x);
        const float2 kb = __half22float2(*(const __half2*)&kv0.y);
        float p0 = q4.x * ka.x + q4.y * ka.y + q4.z * kb.x + q4.w * kb.y;
        p0 += __shfl_xor_sync(0xffffffffu, p0, 1, 8);
        p0 += __shfl_xor_sync(0xffffffffu, p0, 2, 8);
        p0 += __shfl_xor_sync(0xffffffffu, p0, 4, 8);
        const float w = __expf(p0);
        const float2 va = __half22float2(*(const __half2*)&kv0.z);
        const float2 vb = __half22float2(*(const __half2*)&kv0.w);
        den += w;
        acc.x = fmaf(w, va.x, acc.x);
        acc.y = fmaf(w, va.y, acc.y);
        acc.z = fmaf(w, vb.x, acc.z);
        acc.w = fmaf(w, vb.y, acc.w);
    }

    const float inv = (den > 0.f) ? (1.0f / den) : 0.f;
    float4 sk;
    {
        const uint2 su = *(const uint2*)(g_skh + (size_t)node * 128 + lane * 4);
        const float2 sa = __half22float2(*(const __half2*)&su.x);
        const float2 sb2 = __half22float2(*(const __half2*)&su.y);
        sk = make_float4(sa.x, sa.y, sb2.x, sb2.y);
    }
    float4 o;
    o.x = fmaxf(fmaf(acc.x, inv, sk.x), 0.f);
    o.y = fmaxf(fmaf(acc.y, inv, sk.y), 0.f);
    o.z = fmaxf(fmaf(acc.z, inv, sk.z), 0.f);
    o.w = fmaxf(fmaf(acc.w, inv, sk.w), 0.f);
    *(float4*)(out + (size_t)node * 128 + lane * 4) = o;
}

// ---------------- host launcher ----------------
extern "C" void kernel_launch(void* const* d_in, const int* in_sizes, int n_in,
                              void* d_out, int out_size)
{
    const float* x  = (const float*)d_in[0];
    const int*   ei = (const int*)  d_in[1];
    const float* Wq = (const float*)d_in[2];
    const float* bq = (const float*)d_in[3];
    const float* Wk = (const float*)d_in[4];
    const float* bk = (const float*)d_in[5];
    const float* Wv = (const float*)d_in[6];
    const float* bv = (const float*)d_in[7];
    const float* Ws = (const float*)d_in[8];
    const float* bs = (const float*)d_in[9];
    float* out = (float*)d_out;

    const int n = in_sizes[0] / FDIM;   // 50000
    const int e = in_sizes[1] / 2;      // 800000
    const int nb = (n + SCAN_BLK - 1) / SCAN_BLK;

    // Side stream: CSR build overlaps convert + GEMM.
    cudaStream_t s2;
    cudaEvent_t ev0, ev1;
    cudaStreamCreateWithFlags(&s2, cudaStreamNonBlocking);
    cudaEventCreateWithFlags(&ev0, cudaEventDisableTiming);
    cudaEventCreateWithFlags(&ev1, cudaEventDisableTiming);

    cudaEventRecord(ev0, 0);
    cudaStreamWaitEvent(s2, ev0, 0);

    zero_counts<<<(n + 255) / 256, 256, 0, s2>>>(n);
    hist_kernel<<<(e + 255) / 256, 256, 0, s2>>>(ei, e);
    scan_blocks<<<nb, SCAN_BLK, 0, s2>>>(n);
    scan_tops<<<1, SCAN_BLK, 0, s2>>>(nb, n);
    add_offsets<<<(n + 255) / 256, 256, 0, s2>>>(n);
    scatter_kernel<<<(e + 255) / 256, 256, 0, s2>>>(ei, e);
    cudaEventRecord(ev1, s2);

    // fp16 convert, then pipelined GEMM, on main stream
    const int tot4 = n * (FDIM / 4) + 512 * (FDIM / 4);
    split_all<<<(tot4 + 255) / 256, 256>>>(x, Wq, Wk, Wv, Ws, n);
    dim3 gg((n + 127) / 128, 4);
    gemm_mma<<<gg, 256>>>(bq, bk, bv, bs, n);

    cudaStreamWaitEvent(0, ev1, 0);
    edge_attn<<<(n + EA_WARPS - 1) / EA_WARPS, 256>>>(out, n);
}